// round 15
// baseline (speedup 1.0000x reference)
#include <cuda_runtime.h>
#include <cuda_bf16.h>
#include <cuda_fp16.h>
#include <math.h>
#include <stdint.h>

// Problem constants
#define BQ   4
#define LQ   4096
#define DQ   1024
#define HQ   16
#define HDQ  64
#define MQ   256
#define NTOK (BQ * LQ)   // 16384
#define NH   (BQ * HQ)   // 64

typedef __nv_bfloat16 bf16;

// ---------------- scratch (device globals; no runtime allocation) ----------
__device__ float g_q   [NTOK * DQ];
__device__ float g_k   [NTOK * DQ];
__device__ float g_v   [NTOK * DQ];
__device__ float g_qp  [NH * LQ * MQ];
__device__ float g_kp  [NH * LQ * MQ];
__device__ float g_kv  [NH * MQ * HDQ];
__device__ float g_ksum[NH * MQ];
__device__ float g_z   [NH * LQ];
__device__ float g_x2  [NTOK * DQ];

// split-bf16 activations (attention path, 3-term)
__device__ bf16 g_h_hi   [NTOK * DQ];
__device__ bf16 g_h_lo   [NTOK * DQ];
__device__ bf16 g_attn_hi[NTOK * DQ];
__device__ bf16 g_attn_lo[NTOK * DQ];

// single-fp16 activations (MLP path)
__device__ __half g_h2   [NTOK * DQ];
__device__ __half g_midh [NTOK * 4 * DQ];

// split-bf16 transposed weights [N,K] (attention path)
__device__ bf16 g_wq_hi[DQ * DQ], g_wq_lo[DQ * DQ];
__device__ bf16 g_wk_hi[DQ * DQ], g_wk_lo[DQ * DQ];
__device__ bf16 g_wv_hi[DQ * DQ], g_wv_lo[DQ * DQ];
__device__ bf16 g_wo_hi[DQ * DQ], g_wo_lo[DQ * DQ];
// single-fp16 transposed weights [N,K] (MLP path)
__device__ __half g_w1h[DQ * 4 * DQ];
__device__ __half g_w2h[4 * DQ * DQ];

// ======================= PTX helpers =======================================
__device__ __forceinline__ uint32_t smem_u32(const void* p) {
    uint32_t a;
    asm("{ .reg .u64 t; cvta.to.shared.u64 t, %1; cvt.u32.u64 %0, t; }" : "=r"(a) : "l"(p));
    return a;
}
__device__ __forceinline__ void ldsm4(uint32_t* r, uint32_t addr) {
    asm volatile("ldmatrix.sync.aligned.m8n8.x4.shared.b16 {%0,%1,%2,%3}, [%4];"
        : "=r"(r[0]), "=r"(r[1]), "=r"(r[2]), "=r"(r[3]) : "r"(addr));
}
__device__ __forceinline__ void mma16816(float* d, const uint32_t* a, const uint32_t* b) {
    asm volatile(
        "mma.sync.aligned.m16n8k16.row.col.f32.bf16.bf16.f32 "
        "{%0,%1,%2,%3}, {%4,%5,%6,%7}, {%8,%9}, {%0,%1,%2,%3};"
        : "+f"(d[0]), "+f"(d[1]), "+f"(d[2]), "+f"(d[3])
        : "r"(a[0]), "r"(a[1]), "r"(a[2]), "r"(a[3]), "r"(b[0]), "r"(b[1]));
}
__device__ __forceinline__ void mma16816h(float* d, const uint32_t* a, const uint32_t* b) {
    asm volatile(
        "mma.sync.aligned.m16n8k16.row.col.f32.f16.f16.f32 "
        "{%0,%1,%2,%3}, {%4,%5,%6,%7}, {%8,%9}, {%0,%1,%2,%3};"
        : "+f"(d[0]), "+f"(d[1]), "+f"(d[2]), "+f"(d[3])
        : "r"(a[0]), "r"(a[1]), "r"(a[2]), "r"(a[3]), "r"(b[0]), "r"(b[1]));
}
#define CP_ASYNC16(dst, src) \
    asm volatile("cp.async.cg.shared.global [%0], [%1], 16;" :: "r"(dst), "l"(src))
#define CP_COMMIT() asm volatile("cp.async.commit_group;" ::: "memory")
#define CP_WAIT1()  asm volatile("cp.async.wait_group 1;" ::: "memory")
#define CP_WAIT0()  asm volatile("cp.async.wait_group 0;" ::: "memory")

__device__ __forceinline__ void split_bf16(float v, bf16& hi, bf16& lo) {
    hi = __float2bfloat16(v);
    lo = __float2bfloat16(v - __bfloat162float(hi));
}

// ============ tensor-core GEMM v2: pre-split bf16 operands (3-term) ========
#define PAD    40
#define ARR_B  10240u
#define STAGE_B (4 * ARR_B)

__device__ __forceinline__ void load_stage(
    uint32_t sbase, const bf16* Ahi, const bf16* Alo,
    const bf16* Bhi, const bf16* Blo,
    int m0, int n0, int kt, int K, int tid)
{
#pragma unroll
    for (int half = 0; half < 2; half++) {
        int c = tid + half * 256;
        int row = c >> 2, kc = (c & 3) * 8;
        uint32_t dst = sbase + (uint32_t)(row * PAD + kc) * 2;
        size_t aoff = (size_t)(m0 + row) * K + kt + kc;
        size_t boff = (size_t)(n0 + row) * K + kt + kc;
        CP_ASYNC16(dst,              Ahi + aoff);
        CP_ASYNC16(dst + ARR_B,      Alo + aoff);
        CP_ASYNC16(dst + 2 * ARR_B,  Bhi + boff);
        CP_ASYNC16(dst + 3 * ARR_B,  Blo + boff);
    }
}

template <int MODE>   // 0: +bias -> fp32   1: +bias+res -> fp32
__global__ void __launch_bounds__(256, 2) tc_gemm2(
    const bf16* __restrict__ Ahi, const bf16* __restrict__ Alo,
    const bf16* __restrict__ Bhi, const bf16* __restrict__ Blo,
    const float* __restrict__ bias, const float* __restrict__ res,
    float* __restrict__ C, int N, int K)
{
    extern __shared__ __align__(16) char smem[];
    uint32_t sb = smem_u32(smem);

    int tid = threadIdx.x, wid = tid >> 5, lane = tid & 31;
    int m0 = blockIdx.y * 128, n0 = blockIdx.x * 128;
    int m0w = (wid & 1) * 64;
    int n0w = (wid >> 1) * 32;

    float acc[4][4][4];
#pragma unroll
    for (int i = 0; i < 4; i++)
#pragma unroll
        for (int j = 0; j < 4; j++)
#pragma unroll
            for (int q = 0; q < 4; q++) acc[i][j][q] = 0.f;

    int aRowOff = ((lane >> 3) & 1) * 8 + (lane & 7);
    int aKOff   = (lane >> 4) * 8;
    int bNOff   = (lane >> 4) * 8 + (lane & 7);
    int bKOff   = ((lane >> 3) & 1) * 8;

    int KT = K / 32;
    load_stage(sb, Ahi, Alo, Bhi, Blo, m0, n0, 0, K, tid);
    CP_COMMIT();

    for (int kt = 0; kt < KT; kt++) {
        if (kt + 1 < KT) {
            load_stage(sb + ((kt + 1) & 1) * STAGE_B, Ahi, Alo, Bhi, Blo,
                       m0, n0, (kt + 1) * 32, K, tid);
            CP_COMMIT();
            CP_WAIT1();
        } else {
            CP_WAIT0();
        }
        __syncthreads();

        uint32_t st = sb + (kt & 1) * STAGE_B;
#pragma unroll
        for (int ks = 0; ks < 32; ks += 16) {
            uint32_t Ah[4][4], Al[4][4], Bh[2][4], Bl[2][4];
#pragma unroll
            for (int mi = 0; mi < 4; mi++) {
                uint32_t off = (uint32_t)((m0w + mi * 16 + aRowOff) * PAD + ks + aKOff) * 2;
                ldsm4(Ah[mi], st + off);
                ldsm4(Al[mi], st + ARR_B + off);
            }
#pragma unroll
            for (int np = 0; np < 2; np++) {
                uint32_t off = (uint32_t)((n0w + np * 16 + bNOff) * PAD + ks + bKOff) * 2;
                ldsm4(Bh[np], st + 2 * ARR_B + off);
                ldsm4(Bl[np], st + 3 * ARR_B + off);
            }
#pragma unroll
            for (int mi = 0; mi < 4; mi++)
#pragma unroll
                for (int ni = 0; ni < 4; ni++) {
                    const uint32_t* bh = &Bh[ni >> 1][(ni & 1) * 2];
                    const uint32_t* bl = &Bl[ni >> 1][(ni & 1) * 2];
                    mma16816(acc[mi][ni], Ah[mi], bh);
                    mma16816(acc[mi][ni], Al[mi], bh);
                    mma16816(acc[mi][ni], Ah[mi], bl);
                }
        }
        __syncthreads();
    }

    int rOff = lane >> 2;
    int cOff = (lane & 3) * 2;
#pragma unroll
    for (int mi = 0; mi < 4; mi++)
#pragma unroll
        for (int ni = 0; ni < 4; ni++) {
            int col = n0 + n0w + ni * 8 + cOff;
            float b0 = bias[col], b1 = bias[col + 1];
#pragma unroll
            for (int half = 0; half < 2; half++) {
                int row = m0 + m0w + mi * 16 + rOff + half * 8;
                size_t off = (size_t)row * N + col;
                float v0 = acc[mi][ni][half * 2 + 0] + b0;
                float v1 = acc[mi][ni][half * 2 + 1] + b1;
                if (MODE == 1) { v0 += res[off]; v1 += res[off + 1]; }
                float2 o; o.x = v0; o.y = v1;
                *(float2*)(C + off) = o;
            }
        }
}

// ============ tc_gemm_h: single-fp16 operands (MLP path) ===================
#define HSTAGE_B (2 * ARR_B)   // A + B arrays, 20KB per stage

__device__ __forceinline__ void load_stage_h(
    uint32_t sbase, const __half* A, const __half* B,
    int m0, int n0, int kt, int K, int tid)
{
#pragma unroll
    for (int half = 0; half < 2; half++) {
        int c = tid + half * 256;
        int row = c >> 2, kc = (c & 3) * 8;
        uint32_t dst = sbase + (uint32_t)(row * PAD + kc) * 2;
        size_t aoff = (size_t)(m0 + row) * K + kt + kc;
        size_t boff = (size_t)(n0 + row) * K + kt + kc;
        CP_ASYNC16(dst,         A + aoff);
        CP_ASYNC16(dst + ARR_B, B + boff);
    }
}

template <int MODE>   // 1: +bias+res -> fp32 C   2: gelu(+bias) -> fp16 Ch
__global__ void __launch_bounds__(256, 2) tc_gemm_h(
    const __half* __restrict__ A, const __half* __restrict__ B,
    const float* __restrict__ bias, const float* __restrict__ res,
    float* __restrict__ C, __half* __restrict__ Ch,
    int N, int K)
{
    extern __shared__ __align__(16) char smem[];
    uint32_t sb = smem_u32(smem);

    int tid = threadIdx.x, wid = tid >> 5, lane = tid & 31;
    int m0 = blockIdx.y * 128, n0 = blockIdx.x * 128;
    int m0w = (wid & 1) * 64;
    int n0w = (wid >> 1) * 32;

    float acc[4][4][4];
#pragma unroll
    for (int i = 0; i < 4; i++)
#pragma unroll
        for (int j = 0; j < 4; j++)
#pragma unroll
            for (int q = 0; q < 4; q++) acc[i][j][q] = 0.f;

    int aRowOff = ((lane >> 3) & 1) * 8 + (lane & 7);
    int aKOff   = (lane >> 4) * 8;
    int bNOff   = (lane >> 4) * 8 + (lane & 7);
    int bKOff   = ((lane >> 3) & 1) * 8;

    int KT = K / 32;
    load_stage_h(sb, A, B, m0, n0, 0, K, tid);
    CP_COMMIT();

    for (int kt = 0; kt < KT; kt++) {
        if (kt + 1 < KT) {
            load_stage_h(sb + ((kt + 1) & 1) * HSTAGE_B, A, B,
                         m0, n0, (kt + 1) * 32, K, tid);
            CP_COMMIT();
            CP_WAIT1();
        } else {
            CP_WAIT0();
        }
        __syncthreads();

        uint32_t st = sb + (kt & 1) * HSTAGE_B;
#pragma unroll
        for (int ks = 0; ks < 32; ks += 16) {
            uint32_t Af[4][4], Bf[2][4];
#pragma unroll
            for (int mi = 0; mi < 4; mi++) {
                uint32_t off = (uint32_t)((m0w + mi * 16 + aRowOff) * PAD + ks + aKOff) * 2;
                ldsm4(Af[mi], st + off);
            }
#pragma unroll
            for (int np = 0; np < 2; np++) {
                uint32_t off = (uint32_t)((n0w + np * 16 + bNOff) * PAD + ks + bKOff) * 2;
                ldsm4(Bf[np], st + ARR_B + off);
            }
#pragma unroll
            for (int mi = 0; mi < 4; mi++)
#pragma unroll
                for (int ni = 0; ni < 4; ni++)
                    mma16816h(acc[mi][ni], Af[mi], &Bf[ni >> 1][(ni & 1) * 2]);
        }
        __syncthreads();
    }

    int rOff = lane >> 2;
    int cOff = (lane & 3) * 2;
#pragma unroll
    for (int mi = 0; mi < 4; mi++)
#pragma unroll
        for (int ni = 0; ni < 4; ni++) {
            int col = n0 + n0w + ni * 8 + cOff;
            float b0 = bias[col], b1 = bias[col + 1];
#pragma unroll
            for (int half = 0; half < 2; half++) {
                int row = m0 + m0w + mi * 16 + rOff + half * 8;
                size_t off = (size_t)row * N + col;
                float v0 = acc[mi][ni][half * 2 + 0] + b0;
                float v1 = acc[mi][ni][half * 2 + 1] + b1;
                if (MODE == 1) {
                    v0 += res[off]; v1 += res[off + 1];
                    float2 o; o.x = v0; o.y = v1;
                    *(float2*)(C + off) = o;
                } else {
                    v0 = 0.5f * v0 * (1.f + erff(v0 * 0.70710678118654752f));
                    v1 = 0.5f * v1 * (1.f + erff(v1 * 0.70710678118654752f));
                    __half2 hp = __floats2half2_rn(v0, v1);
                    *(uint32_t*)(Ch + off) = *(uint32_t*)&hp;
                }
            }
        }
}

// ---------------- weight transpose+split (bf16 hi/lo) ----------------------
__global__ void __launch_bounds__(256) wconv_kernel(
    const float* __restrict__ W, bf16* __restrict__ hi, bf16* __restrict__ lo,
    int K, int N)
{
    __shared__ float tile[32][33];
    int k0 = blockIdx.y * 32, n0 = blockIdx.x * 32;
    int tx = threadIdx.x & 31, ty = threadIdx.x >> 5;
#pragma unroll
    for (int i = ty; i < 32; i += 8)
        tile[i][tx] = W[(size_t)(k0 + i) * N + n0 + tx];
    __syncthreads();
#pragma unroll
    for (int i = ty; i < 32; i += 8) {
        float v = tile[tx][i];
        bf16 h, l;
        split_bf16(v, h, l);
        size_t off = (size_t)(n0 + i) * K + k0 + tx;
        hi[off] = h; lo[off] = l;
    }
}

// ---------------- weight transpose (single fp16) ---------------------------
__global__ void __launch_bounds__(256) wconv_h_kernel(
    const float* __restrict__ W, __half* __restrict__ out, int K, int N)
{
    __shared__ float tile[32][33];
    int k0 = blockIdx.y * 32, n0 = blockIdx.x * 32;
    int tx = threadIdx.x & 31, ty = threadIdx.x >> 5;
#pragma unroll
    for (int i = ty; i < 32; i += 8)
        tile[i][tx] = W[(size_t)(k0 + i) * N + n0 + tx];
    __syncthreads();
#pragma unroll
    for (int i = ty; i < 32; i += 8)
        out[(size_t)(n0 + i) * K + k0 + tx] = __float2half(tile[tx][i]);
}

// ---------------- LayerNorm -> split bf16 ----------------------------------
__global__ void __launch_bounds__(256) ln_kernel(
    const float* __restrict__ x, const float* __restrict__ w,
    const float* __restrict__ b, bf16* __restrict__ out_hi, bf16* __restrict__ out_lo)
{
    int row = blockIdx.x;
    int t = threadIdx.x;
    const float* xr = x + (size_t)row * DQ;
    float v0[4];
    float s = 0.f, sq = 0.f;
#pragma unroll
    for (int i = 0; i < 4; i++) {
        float val = xr[t + i * 256];
        v0[i] = val; s += val; sq = fmaf(val, val, sq);
    }
    __shared__ float ss[8], ssq[8];
    __shared__ float mu_s, rs_s;
#pragma unroll
    for (int o = 16; o > 0; o >>= 1) {
        s  += __shfl_xor_sync(0xffffffffu, s, o);
        sq += __shfl_xor_sync(0xffffffffu, sq, o);
    }
    if ((t & 31) == 0) { ss[t >> 5] = s; ssq[t >> 5] = sq; }
    __syncthreads();
    if (t < 32) {
        float a  = (t < 8) ? ss[t]  : 0.f;
        float aq = (t < 8) ? ssq[t] : 0.f;
#pragma unroll
        for (int o = 4; o > 0; o >>= 1) {
            a  += __shfl_xor_sync(0xffffffffu, a, o);
            aq += __shfl_xor_sync(0xffffffffu, aq, o);
        }
        if (t == 0) {
            float mu = a * (1.f / DQ);
            float var = aq * (1.f / DQ) - mu * mu;
            mu_s = mu; rs_s = rsqrtf(var + 1e-5f);
        }
    }
    __syncthreads();
    float mu = mu_s, rs = rs_s;
#pragma unroll
    for (int i = 0; i < 4; i++) {
        int c = t + i * 256;
        float v = (v0[i] - mu) * rs * w[c] + b[c];
        bf16 h, l;
        split_bf16(v, h, l);
        out_hi[(size_t)row * DQ + c] = h;
        out_lo[(size_t)row * DQ + c] = l;
    }
}

// ---------------- LayerNorm -> single fp16 ---------------------------------
__global__ void __launch_bounds__(256) ln_kernel_h(
    const float* __restrict__ x, const float* __restrict__ w,
    const float* __restrict__ b, __half* __restrict__ out_h)
{
    int row = blockIdx.x;
    int t = threadIdx.x;
    const float* xr = x + (size_t)row * DQ;
    float v0[4];
    float s = 0.f, sq = 0.f;
#pragma unroll
    for (int i = 0; i < 4; i++) {
        float val = xr[t + i * 256];
        v0[i] = val; s += val; sq = fmaf(val, val, sq);
    }
    __shared__ float ss[8], ssq[8];
    __shared__ float mu_s, rs_s;
#pragma unroll
    for (int o = 16; o > 0; o >>= 1) {
        s  += __shfl_xor_sync(0xffffffffu, s, o);
        sq += __shfl_xor_sync(0xffffffffu, sq, o);
    }
    if ((t & 31) == 0) { ss[t >> 5] = s; ssq[t >> 5] = sq; }
    __syncthreads();
    if (t < 32) {
        float a  = (t < 8) ? ss[t]  : 0.f;
        float aq = (t < 8) ? ssq[t] : 0.f;
#pragma unroll
        for (int o = 4; o > 0; o >>= 1) {
            a  += __shfl_xor_sync(0xffffffffu, a, o);
            aq += __shfl_xor_sync(0xffffffffu, aq, o);
        }
        if (t == 0) {
            float mu = a * (1.f / DQ);
            float var = aq * (1.f / DQ) - mu * mu;
            mu_s = mu; rs_s = rsqrtf(var + 1e-5f);
        }
    }
    __syncthreads();
    float mu = mu_s, rs = rs_s;
#pragma unroll
    for (int i = 0; i < 4; i++) {
        int c = t + i * 256;
        float v = (v0[i] - mu) * rs * w[c] + b[c];
        out_h[(size_t)row * DQ + c] = __float2half(v);
    }
}

// ------------- performer feature map ---------------------------------------
__global__ void __launch_bounds__(256) feature_kernel(
    const float* __restrict__ src, const float* __restrict__ proj,
    float* __restrict__ dst)
{
    int bh = blockIdx.y;
    int h = bh & (HQ - 1), b = bh >> 4;
    int l0 = blockIdx.x * 64;
    __shared__ float data[64][HDQ + 1];
    __shared__ float pt[64][HDQ + 1];
    __shared__ float sqs[64];
    const float scale = 0.35355339059327373f;
    int tid = threadIdx.x;

    for (int idx = tid; idx < 64 * 64; idx += 256) {
        int t = idx >> 6, d = idx & 63;
        data[t][d] = src[(size_t)(b * LQ + l0 + t) * DQ + h * HDQ + d] * scale;
    }
    __syncthreads();
    if (tid < 64) {
        float s = 0.f;
#pragma unroll 8
        for (int d = 0; d < 64; d++) { float v = data[tid][d]; s = fmaf(v, v, s); }
        sqs[tid] = 0.5f * s;
    }

    int tt = (tid >> 4) << 2;
    int mm = (tid & 15) << 2;

    for (int mt = 0; mt < MQ; mt += 64) {
        __syncthreads();
        for (int idx = tid; idx < 64 * 64; idx += 256) {
            int m = idx >> 6, d = idx & 63;
            pt[m][d] = proj[(size_t)(mt + m) * HDQ + d];
        }
        __syncthreads();
        float acc[4][4];
#pragma unroll
        for (int i = 0; i < 4; i++)
#pragma unroll
            for (int j = 0; j < 4; j++) acc[i][j] = 0.f;
        for (int d = 0; d < 64; d++) {
            float a[4], bb[4];
#pragma unroll
            for (int i = 0; i < 4; i++) a[i] = data[tt + i][d];
#pragma unroll
            for (int j = 0; j < 4; j++) bb[j] = pt[mm + j][d];
#pragma unroll
            for (int i = 0; i < 4; i++)
#pragma unroll
                for (int j = 0; j < 4; j++)
                    acc[i][j] = fmaf(a[i], bb[j], acc[i][j]);
        }
#pragma unroll
        for (int i = 0; i < 4; i++) {
            float sv = sqs[tt + i];
            size_t orow = ((size_t)bh * LQ + l0 + tt + i) * MQ + mt + mm;
#pragma unroll
            for (int j = 0; j < 4; j++)
                dst[orow + j] = expf(acc[i][j] - sv + 1e-6f);
        }
    }
}

// ---------------- kv = k_p^T @ v + k_sum (split-K atomics) -----------------
__global__ void __launch_bounds__(256) kv_kernel(
    const float* __restrict__ kp, const float* __restrict__ v)
{
    const int SPL = 8;
    int bh = blockIdx.y;
    int h = bh & (HQ - 1), b = bh >> 4;
    int lbase = blockIdx.x * (LQ / SPL);
    __shared__ float kps[16][MQ];
    __shared__ float vs[16][HDQ + 4];
    int tid = threadIdx.x;
    int mi = (tid >> 3) << 3;
    int di = (tid & 7) << 3;
    float acc[8][8];
    float ks[8];
#pragma unroll
    for (int i = 0; i < 8; i++) {
        ks[i] = 0.f;
#pragma unroll
        for (int j = 0; j < 8; j++) acc[i][j] = 0.f;
    }
    bool owner = ((tid & 7) == 0);

    for (int lc = 0; lc < LQ / SPL; lc += 16) {
        for (int idx = tid; idx < 16 * 64; idx += 256) {
            int l = idx >> 6, m4 = (idx & 63) * 4;
            *(float4*)&kps[l][m4] =
                *(const float4*)(kp + ((size_t)bh * LQ + lbase + lc + l) * MQ + m4);
        }
        for (int idx = tid; idx < 16 * 16; idx += 256) {
            int l = idx >> 4, d4 = (idx & 15) * 4;
            *(float4*)&vs[l][d4] =
                *(const float4*)(v + (size_t)(b * LQ + lbase + lc + l) * DQ + h * HDQ + d4);
        }
        __syncthreads();
#pragma unroll
        for (int l = 0; l < 16; l++) {
            float a[8], bb[8];
#pragma unroll
            for (int i = 0; i < 8; i++) a[i] = kps[l][mi + i];
#pragma unroll
            for (int j = 0; j < 8; j++) bb[j] = vs[l][di + j];
#pragma unroll
            for (int i = 0; i < 8; i++)
#pragma unroll
                for (int j = 0; j < 8; j++)
                    acc[i][j] = fmaf(a[i], bb[j], acc[i][j]);
            if (owner)
#pragma unroll
                for (int i = 0; i < 8; i++) ks[i] += a[i];
        }
        __syncthreads();
    }
#pragma unroll
    for (int i = 0; i < 8; i++)
#pragma unroll
        for (int j = 0; j < 8; j++)
            atomicAdd(&g_kv[((size_t)bh * MQ + mi + i) * HDQ + di + j], acc[i][j]);
    if (owner)
#pragma unroll
        for (int i = 0; i < 8; i++)
            atomicAdd(&g_ksum[bh * MQ + mi + i], ks[i]);
}

// ---------------- z ----------------
__global__ void __launch_bounds__(256) z_kernel(const float* __restrict__ qp)
{
    int row = blockIdx.x * 8 + (threadIdx.x >> 5);
    int lane = threadIdx.x & 31;
    int bh = row >> 12;
    const float* qr = qp + (size_t)row * MQ;
    const float* kss = g_ksum + bh * MQ;
    float s = 0.f;
#pragma unroll
    for (int m = lane; m < MQ; m += 32) s = fmaf(qr[m], kss[m], s);
#pragma unroll
    for (int o = 16; o > 0; o >>= 1) s += __shfl_xor_sync(0xffffffffu, s, o);
    if (lane == 0) g_z[row] = 1.f / (s + 1e-6f);
}

// ---------------- attn combine -> split bf16 -------------------------------
__global__ void __launch_bounds__(256) attn_kernel(
    const float* __restrict__ qp, bf16* __restrict__ out_hi, bf16* __restrict__ out_lo)
{
    int bh = blockIdx.y;
    int h = bh & (HQ - 1), b = bh >> 4;
    int l0 = blockIdx.x * 128;
    __shared__ float qs[128][36];
    __shared__ float kvs[32][HDQ + 4];
    int tid = threadIdx.x;
    int ti = (tid >> 3) << 2;
    int di = (tid & 7) << 3;
    float acc[4][8];
#pragma unroll
    for (int i = 0; i < 4; i++)
#pragma unroll
        for (int j = 0; j < 8; j++) acc[i][j] = 0.f;

    for (int m0 = 0; m0 < MQ; m0 += 32) {
        for (int idx = tid; idx < 128 * 8; idx += 256) {
            int t = idx >> 3, mq = (idx & 7) * 4;
            *(float4*)&qs[t][mq] =
                *(const float4*)(qp + ((size_t)bh * LQ + l0 + t) * MQ + m0 + mq);
        }
        for (int idx = tid; idx < 32 * 16; idx += 256) {
            int m = idx >> 4, dq = (idx & 15) * 4;
            *(float4*)&kvs[m][dq] =
                *(const float4*)(&g_kv[((size_t)bh * MQ + m0 + m) * HDQ + dq]);
        }
        __syncthreads();
#pragma unroll 4
        for (int m = 0; m < 32; m++) {
            float a[4], bb[8];
#pragma unroll
            for (int i = 0; i < 4; i++) a[i] = qs[ti + i][m];
#pragma unroll
            for (int j = 0; j < 8; j++) bb[j] = kvs[m][di + j];
#pragma unroll
            for (int i = 0; i < 4; i++)
#pragma unroll
                for (int j = 0; j < 8; j++)
                    acc[i][j] = fmaf(a[i], bb[j], acc[i][j]);
        }
        __syncthreads();
    }
#pragma unroll
    for (int i = 0; i < 4; i++) {
        float zz = g_z[bh * LQ + l0 + ti + i];
        size_t token = (size_t)(b * LQ + l0 + ti + i);
        size_t base = token * DQ + h * HDQ + di;
#pragma unroll
        for (int j = 0; j < 8; j += 2) {
            float v0 = acc[i][j] * zz, v1 = acc[i][j + 1] * zz;
            bf16 h0, l0b, h1, l1;
            split_bf16(v0, h0, l0b);
            split_bf16(v1, h1, l1);
            *(uint32_t*)(out_hi + base + j) =
                (uint32_t)__bfloat16_as_ushort(h0) | ((uint32_t)__bfloat16_as_ushort(h1) << 16);
            *(uint32_t*)(out_lo + base + j) =
                (uint32_t)__bfloat16_as_ushort(l0b) | ((uint32_t)__bfloat16_as_ushort(l1) << 16);
        }
    }
}

// ---------------------------------------------------------------------------
extern "C" void kernel_launch(void* const* d_in, const int* in_sizes, int n_in,
                              void* d_out, int out_size)
{
    const float* x     = (const float*)d_in[0];
    const float* ln1_w = (const float*)d_in[1];
    const float* ln1_b = (const float*)d_in[2];
    const float* ln2_w = (const float*)d_in[3];
    const float* ln2_b = (const float*)d_in[4];
    const float* Wq    = (const float*)d_in[5];
    const float* bq    = (const float*)d_in[6];
    const float* Wk    = (const float*)d_in[7];
    const float* bk    = (const float*)d_in[8];
    const float* Wv    = (const float*)d_in[9];
    const float* bv    = (const float*)d_in[10];
    const float* Wo    = (const float*)d_in[11];
    const float* bo    = (const float*)d_in[12];
    const float* W1    = (const float*)d_in[13];
    const float* b1    = (const float*)d_in[14];
    const float* W2    = (const float*)d_in[15];
    const float* b2    = (const float*)d_in[16];
    const float* proj  = (const float*)d_in[17];
    float* out = (float*)d_out;

    float *p_q, *p_k, *p_v, *p_qp, *p_kp, *p_kv, *p_ksum, *p_x2;
    bf16 *p_hh, *p_hl, *p_ah, *p_al;
    __half *p_h2, *p_midh, *p_w1h, *p_w2h;
    bf16 *p_wq_h, *p_wq_l, *p_wk_h, *p_wk_l, *p_wv_h, *p_wv_l, *p_wo_h, *p_wo_l;
    cudaGetSymbolAddress((void**)&p_q,    g_q);
    cudaGetSymbolAddress((void**)&p_k,    g_k);
    cudaGetSymbolAddress((void**)&p_v,    g_v);
    cudaGetSymbolAddress((void**)&p_qp,   g_qp);
    cudaGetSymbolAddress((void**)&p_kp,   g_kp);
    cudaGetSymbolAddress((void**)&p_kv,   g_kv);
    cudaGetSymbolAddress((void**)&p_ksum, g_ksum);
    cudaGetSymbolAddress((void**)&p_x2,   g_x2);
    cudaGetSymbolAddress((void**)&p_hh,   g_h_hi);
    cudaGetSymbolAddress((void**)&p_hl,   g_h_lo);
    cudaGetSymbolAddress((void**)&p_ah,   g_attn_hi);
    cudaGetSymbolAddress((void**)&p_al,   g_attn_lo);
    cudaGetSymbolAddress((void**)&p_h2,   g_h2);
    cudaGetSymbolAddress((void**)&p_midh, g_midh);
    cudaGetSymbolAddress((void**)&p_w1h,  g_w1h);
    cudaGetSymbolAddress((void**)&p_w2h,  g_w2h);
    cudaGetSymbolAddress((void**)&p_wq_h, g_wq_hi); cudaGetSymbolAddress((void**)&p_wq_l, g_wq_lo);
    cudaGetSymbolAddress((void**)&p_wk_h, g_wk_hi); cudaGetSymbolAddress((void**)&p_wk_l, g_wk_lo);
    cudaGetSymbolAddress((void**)&p_wv_h, g_wv_hi); cudaGetSymbolAddress((void**)&p_wv_l, g_wv_lo);
    cudaGetSymbolAddress((void**)&p_wo_h, g_wo_hi); cudaGetSymbolAddress((void**)&p_wo_l, g_wo_lo);

    const int SMEM_GEMM = 2 * STAGE_B;      // 80KB
    const int SMEM_H    = 2 * HSTAGE_B;     // 40KB
    cudaFuncSetAttribute(tc_gemm2<0>, cudaFuncAttributeMaxDynamicSharedMemorySize, SMEM_GEMM);
    cudaFuncSetAttribute(tc_gemm2<1>, cudaFuncAttributeMaxDynamicSharedMemorySize, SMEM_GEMM);
    cudaFuncSetAttribute(tc_gemm_h<1>, cudaFuncAttributeMaxDynamicSharedMemorySize, SMEM_H);
    cudaFuncSetAttribute(tc_gemm_h<2>, cudaFuncAttributeMaxDynamicSharedMemorySize, SMEM_H);

    dim3 gD(DQ / 128, NTOK / 128);
    dim3 g4D(4 * DQ / 128, NTOK / 128);

    // weight conversions
    wconv_kernel<<<dim3(DQ / 32, DQ / 32), 256>>>(Wq, p_wq_h, p_wq_l, DQ, DQ);
    wconv_kernel<<<dim3(DQ / 32, DQ / 32), 256>>>(Wk, p_wk_h, p_wk_l, DQ, DQ);
    wconv_kernel<<<dim3(DQ / 32, DQ / 32), 256>>>(Wv, p_wv_h, p_wv_l, DQ, DQ);
    wconv_kernel<<<dim3(DQ / 32, DQ / 32), 256>>>(Wo, p_wo_h, p_wo_l, DQ, DQ);
    wconv_h_kernel<<<dim3(4 * DQ / 32, DQ / 32), 256>>>(W1, p_w1h, DQ, 4 * DQ);
    wconv_h_kernel<<<dim3(DQ / 32, 4 * DQ / 32), 256>>>(W2, p_w2h, 4 * DQ, DQ);

    // LN1 -> split h
    ln_kernel<<<NTOK, 256>>>(x, ln1_w, ln1_b, p_hh, p_hl);
    // QKV (bf16 3-term)
    tc_gemm2<0><<<gD, 256, SMEM_GEMM>>>(p_hh, p_hl, p_wq_h, p_wq_l, bq, nullptr, p_q, DQ, DQ);
    tc_gemm2<0><<<gD, 256, SMEM_GEMM>>>(p_hh, p_hl, p_wk_h, p_wk_l, bk, nullptr, p_k, DQ, DQ);
    tc_gemm2<0><<<gD, 256, SMEM_GEMM>>>(p_hh, p_hl, p_wv_h, p_wv_l, bv, nullptr, p_v, DQ, DQ);
    // performer feature maps
    feature_kernel<<<dim3(LQ / 64, NH), 256>>>(p_q, proj, p_qp);
    feature_kernel<<<dim3(LQ / 64, NH), 256>>>(p_k, proj, p_kp);
    // kv + k_sum
    cudaMemsetAsync(p_kv,   0, (size_t)NH * MQ * HDQ * sizeof(float));
    cudaMemsetAsync(p_ksum, 0, (size_t)NH * MQ * sizeof(float));
    kv_kernel<<<dim3(8, NH), 256>>>(p_kp, p_v);
    // normalizer z
    z_kernel<<<NH * LQ / 8, 256>>>(p_qp);
    // attention combine -> split attn
    attn_kernel<<<dim3(LQ / 128, NH), 256>>>(p_qp, p_ah, p_al);
    // output proj + residual (bf16 3-term)
    tc_gemm2<1><<<gD, 256, SMEM_GEMM>>>(p_ah, p_al, p_wo_h, p_wo_l, bo, x, p_x2, DQ, DQ);
    // LN2 -> single fp16
    ln_kernel_h<<<NTOK, 256>>>(p_x2, ln2_w, ln2_b, p_h2);
    // MLP up + gelu (fp16 single) -> fp16 mid
    tc_gemm_h<2><<<g4D, 256, SMEM_H>>>(p_h2, p_w1h, b1, nullptr, nullptr, p_midh, 4 * DQ, DQ);
    // MLP down + residual (fp16 single) -> out
    tc_gemm_h<1><<<gD, 256, SMEM_H>>>(p_midh, p_w2h, b2, p_x2, out, nullptr, DQ, 4 * DQ);
}

// round 16
// speedup vs baseline: 1.0456x; 1.0456x over previous
#include <cuda_runtime.h>
#include <cuda_bf16.h>
#include <cuda_fp16.h>
#include <math.h>
#include <stdint.h>

// Problem constants
#define BQ   4
#define LQ   4096
#define DQ   1024
#define HQ   16
#define HDQ  64
#define MQ   256
#define NTOK (BQ * LQ)   // 16384
#define NH   (BQ * HQ)   // 64

typedef __nv_bfloat16 bf16;

// ---------------- scratch (device globals; no runtime allocation) ----------
__device__ float g_q   [NTOK * DQ];
__device__ float g_k   [NTOK * DQ];
__device__ float g_v   [NTOK * DQ];
__device__ bf16  g_qp  [NH * LQ * MQ];   // bf16 features (128 MB)
__device__ bf16  g_kp  [NH * LQ * MQ];
__device__ float g_kv  [NH * MQ * HDQ];
__device__ float g_ksum[NH * MQ];
__device__ float g_z   [NH * LQ];
__device__ float g_x2  [NTOK * DQ];

// split-bf16 activations (attention path, 3-term)
__device__ bf16 g_h_hi   [NTOK * DQ];
__device__ bf16 g_h_lo   [NTOK * DQ];
__device__ bf16 g_attn_hi[NTOK * DQ];
__device__ bf16 g_attn_lo[NTOK * DQ];

// single-fp16 activations (MLP path)
__device__ __half g_h2   [NTOK * DQ];
__device__ __half g_midh [NTOK * 4 * DQ];

// split-bf16 transposed weights [N,K] (attention path)
__device__ bf16 g_wq_hi[DQ * DQ], g_wq_lo[DQ * DQ];
__device__ bf16 g_wk_hi[DQ * DQ], g_wk_lo[DQ * DQ];
__device__ bf16 g_wv_hi[DQ * DQ], g_wv_lo[DQ * DQ];
__device__ bf16 g_wo_hi[DQ * DQ], g_wo_lo[DQ * DQ];
// single-fp16 transposed weights [N,K] (MLP path)
__device__ __half g_w1h[DQ * 4 * DQ];
__device__ __half g_w2h[4 * DQ * DQ];

// ======================= PTX helpers =======================================
__device__ __forceinline__ uint32_t smem_u32(const void* p) {
    uint32_t a;
    asm("{ .reg .u64 t; cvta.to.shared.u64 t, %1; cvt.u32.u64 %0, t; }" : "=r"(a) : "l"(p));
    return a;
}
__device__ __forceinline__ void ldsm4(uint32_t* r, uint32_t addr) {
    asm volatile("ldmatrix.sync.aligned.m8n8.x4.shared.b16 {%0,%1,%2,%3}, [%4];"
        : "=r"(r[0]), "=r"(r[1]), "=r"(r[2]), "=r"(r[3]) : "r"(addr));
}
__device__ __forceinline__ void mma16816(float* d, const uint32_t* a, const uint32_t* b) {
    asm volatile(
        "mma.sync.aligned.m16n8k16.row.col.f32.bf16.bf16.f32 "
        "{%0,%1,%2,%3}, {%4,%5,%6,%7}, {%8,%9}, {%0,%1,%2,%3};"
        : "+f"(d[0]), "+f"(d[1]), "+f"(d[2]), "+f"(d[3])
        : "r"(a[0]), "r"(a[1]), "r"(a[2]), "r"(a[3]), "r"(b[0]), "r"(b[1]));
}
__device__ __forceinline__ void mma16816h(float* d, const uint32_t* a, const uint32_t* b) {
    asm volatile(
        "mma.sync.aligned.m16n8k16.row.col.f32.f16.f16.f32 "
        "{%0,%1,%2,%3}, {%4,%5,%6,%7}, {%8,%9}, {%0,%1,%2,%3};"
        : "+f"(d[0]), "+f"(d[1]), "+f"(d[2]), "+f"(d[3])
        : "r"(a[0]), "r"(a[1]), "r"(a[2]), "r"(a[3]), "r"(b[0]), "r"(b[1]));
}
#define CP_ASYNC16(dst, src) \
    asm volatile("cp.async.cg.shared.global [%0], [%1], 16;" :: "r"(dst), "l"(src))
#define CP_COMMIT() asm volatile("cp.async.commit_group;" ::: "memory")
#define CP_WAIT1()  asm volatile("cp.async.wait_group 1;" ::: "memory")
#define CP_WAIT0()  asm volatile("cp.async.wait_group 0;" ::: "memory")

__device__ __forceinline__ void split_bf16(float v, bf16& hi, bf16& lo) {
    hi = __float2bfloat16(v);
    lo = __float2bfloat16(v - __bfloat162float(hi));
}
__device__ __forceinline__ uint32_t packbf2(float a, float b) {
    __nv_bfloat162 t = __floats2bfloat162_rn(a, b);
    return *reinterpret_cast<uint32_t*>(&t);
}

// ============ tensor-core GEMM v2: pre-split bf16 operands (3-term) ========
#define PAD    40
#define ARR_B  10240u
#define STAGE_B (4 * ARR_B)

__device__ __forceinline__ void load_stage(
    uint32_t sbase, const bf16* Ahi, const bf16* Alo,
    const bf16* Bhi, const bf16* Blo,
    int m0, int n0, int kt, int K, int tid)
{
#pragma unroll
    for (int half = 0; half < 2; half++) {
        int c = tid + half * 256;
        int row = c >> 2, kc = (c & 3) * 8;
        uint32_t dst = sbase + (uint32_t)(row * PAD + kc) * 2;
        size_t aoff = (size_t)(m0 + row) * K + kt + kc;
        size_t boff = (size_t)(n0 + row) * K + kt + kc;
        CP_ASYNC16(dst,              Ahi + aoff);
        CP_ASYNC16(dst + ARR_B,      Alo + aoff);
        CP_ASYNC16(dst + 2 * ARR_B,  Bhi + boff);
        CP_ASYNC16(dst + 3 * ARR_B,  Blo + boff);
    }
}

template <int MODE>   // 0: +bias -> fp32   1: +bias+res -> fp32
__global__ void __launch_bounds__(256, 2) tc_gemm2(
    const bf16* __restrict__ Ahi, const bf16* __restrict__ Alo,
    const bf16* __restrict__ Bhi, const bf16* __restrict__ Blo,
    const float* __restrict__ bias, const float* __restrict__ res,
    float* __restrict__ C, int N, int K)
{
    extern __shared__ __align__(16) char smem[];
    uint32_t sb = smem_u32(smem);

    int tid = threadIdx.x, wid = tid >> 5, lane = tid & 31;
    int m0 = blockIdx.y * 128, n0 = blockIdx.x * 128;
    int m0w = (wid & 1) * 64;
    int n0w = (wid >> 1) * 32;

    float acc[4][4][4];
#pragma unroll
    for (int i = 0; i < 4; i++)
#pragma unroll
        for (int j = 0; j < 4; j++)
#pragma unroll
            for (int q = 0; q < 4; q++) acc[i][j][q] = 0.f;

    int aRowOff = ((lane >> 3) & 1) * 8 + (lane & 7);
    int aKOff   = (lane >> 4) * 8;
    int bNOff   = (lane >> 4) * 8 + (lane & 7);
    int bKOff   = ((lane >> 3) & 1) * 8;

    int KT = K / 32;
    load_stage(sb, Ahi, Alo, Bhi, Blo, m0, n0, 0, K, tid);
    CP_COMMIT();

    for (int kt = 0; kt < KT; kt++) {
        if (kt + 1 < KT) {
            load_stage(sb + ((kt + 1) & 1) * STAGE_B, Ahi, Alo, Bhi, Blo,
                       m0, n0, (kt + 1) * 32, K, tid);
            CP_COMMIT();
            CP_WAIT1();
        } else {
            CP_WAIT0();
        }
        __syncthreads();

        uint32_t st = sb + (kt & 1) * STAGE_B;
#pragma unroll
        for (int ks = 0; ks < 32; ks += 16) {
            uint32_t Ah[4][4], Al[4][4], Bh[2][4], Bl[2][4];
#pragma unroll
            for (int mi = 0; mi < 4; mi++) {
                uint32_t off = (uint32_t)((m0w + mi * 16 + aRowOff) * PAD + ks + aKOff) * 2;
                ldsm4(Ah[mi], st + off);
                ldsm4(Al[mi], st + ARR_B + off);
            }
#pragma unroll
            for (int np = 0; np < 2; np++) {
                uint32_t off = (uint32_t)((n0w + np * 16 + bNOff) * PAD + ks + bKOff) * 2;
                ldsm4(Bh[np], st + 2 * ARR_B + off);
                ldsm4(Bl[np], st + 3 * ARR_B + off);
            }
#pragma unroll
            for (int mi = 0; mi < 4; mi++)
#pragma unroll
                for (int ni = 0; ni < 4; ni++) {
                    const uint32_t* bh = &Bh[ni >> 1][(ni & 1) * 2];
                    const uint32_t* bl = &Bl[ni >> 1][(ni & 1) * 2];
                    mma16816(acc[mi][ni], Ah[mi], bh);
                    mma16816(acc[mi][ni], Al[mi], bh);
                    mma16816(acc[mi][ni], Ah[mi], bl);
                }
        }
        __syncthreads();
    }

    int rOff = lane >> 2;
    int cOff = (lane & 3) * 2;
#pragma unroll
    for (int mi = 0; mi < 4; mi++)
#pragma unroll
        for (int ni = 0; ni < 4; ni++) {
            int col = n0 + n0w + ni * 8 + cOff;
            float b0 = bias[col], b1 = bias[col + 1];
#pragma unroll
            for (int half = 0; half < 2; half++) {
                int row = m0 + m0w + mi * 16 + rOff + half * 8;
                size_t off = (size_t)row * N + col;
                float v0 = acc[mi][ni][half * 2 + 0] + b0;
                float v1 = acc[mi][ni][half * 2 + 1] + b1;
                if (MODE == 1) { v0 += res[off]; v1 += res[off + 1]; }
                float2 o; o.x = v0; o.y = v1;
                *(float2*)(C + off) = o;
            }
        }
}

// ============ tc_gemm_h: single-fp16 operands (MLP path) ===================
#define HSTAGE_B (2 * ARR_B)

__device__ __forceinline__ void load_stage_h(
    uint32_t sbase, const __half* A, const __half* B,
    int m0, int n0, int kt, int K, int tid)
{
#pragma unroll
    for (int half = 0; half < 2; half++) {
        int c = tid + half * 256;
        int row = c >> 2, kc = (c & 3) * 8;
        uint32_t dst = sbase + (uint32_t)(row * PAD + kc) * 2;
        size_t aoff = (size_t)(m0 + row) * K + kt + kc;
        size_t boff = (size_t)(n0 + row) * K + kt + kc;
        CP_ASYNC16(dst,         A + aoff);
        CP_ASYNC16(dst + ARR_B, B + boff);
    }
}

template <int MODE>   // 1: +bias+res -> fp32 C   2: gelu(+bias) -> fp16 Ch
__global__ void __launch_bounds__(256, 2) tc_gemm_h(
    const __half* __restrict__ A, const __half* __restrict__ B,
    const float* __restrict__ bias, const float* __restrict__ res,
    float* __restrict__ C, __half* __restrict__ Ch,
    int N, int K)
{
    extern __shared__ __align__(16) char smem[];
    uint32_t sb = smem_u32(smem);

    int tid = threadIdx.x, wid = tid >> 5, lane = tid & 31;
    int m0 = blockIdx.y * 128, n0 = blockIdx.x * 128;
    int m0w = (wid & 1) * 64;
    int n0w = (wid >> 1) * 32;

    float acc[4][4][4];
#pragma unroll
    for (int i = 0; i < 4; i++)
#pragma unroll
        for (int j = 0; j < 4; j++)
#pragma unroll
            for (int q = 0; q < 4; q++) acc[i][j][q] = 0.f;

    int aRowOff = ((lane >> 3) & 1) * 8 + (lane & 7);
    int aKOff   = (lane >> 4) * 8;
    int bNOff   = (lane >> 4) * 8 + (lane & 7);
    int bKOff   = ((lane >> 3) & 1) * 8;

    int KT = K / 32;
    load_stage_h(sb, A, B, m0, n0, 0, K, tid);
    CP_COMMIT();

    for (int kt = 0; kt < KT; kt++) {
        if (kt + 1 < KT) {
            load_stage_h(sb + ((kt + 1) & 1) * HSTAGE_B, A, B,
                         m0, n0, (kt + 1) * 32, K, tid);
            CP_COMMIT();
            CP_WAIT1();
        } else {
            CP_WAIT0();
        }
        __syncthreads();

        uint32_t st = sb + (kt & 1) * HSTAGE_B;
#pragma unroll
        for (int ks = 0; ks < 32; ks += 16) {
            uint32_t Af[4][4], Bf[2][4];
#pragma unroll
            for (int mi = 0; mi < 4; mi++) {
                uint32_t off = (uint32_t)((m0w + mi * 16 + aRowOff) * PAD + ks + aKOff) * 2;
                ldsm4(Af[mi], st + off);
            }
#pragma unroll
            for (int np = 0; np < 2; np++) {
                uint32_t off = (uint32_t)((n0w + np * 16 + bNOff) * PAD + ks + bKOff) * 2;
                ldsm4(Bf[np], st + ARR_B + off);
            }
#pragma unroll
            for (int mi = 0; mi < 4; mi++)
#pragma unroll
                for (int ni = 0; ni < 4; ni++)
                    mma16816h(acc[mi][ni], Af[mi], &Bf[ni >> 1][(ni & 1) * 2]);
        }
        __syncthreads();
    }

    int rOff = lane >> 2;
    int cOff = (lane & 3) * 2;
#pragma unroll
    for (int mi = 0; mi < 4; mi++)
#pragma unroll
        for (int ni = 0; ni < 4; ni++) {
            int col = n0 + n0w + ni * 8 + cOff;
            float b0 = bias[col], b1 = bias[col + 1];
#pragma unroll
            for (int half = 0; half < 2; half++) {
                int row = m0 + m0w + mi * 16 + rOff + half * 8;
                size_t off = (size_t)row * N + col;
                float v0 = acc[mi][ni][half * 2 + 0] + b0;
                float v1 = acc[mi][ni][half * 2 + 1] + b1;
                if (MODE == 1) {
                    v0 += res[off]; v1 += res[off + 1];
                    float2 o; o.x = v0; o.y = v1;
                    *(float2*)(C + off) = o;
                } else {
                    v0 = 0.5f * v0 * (1.f + erff(v0 * 0.70710678118654752f));
                    v1 = 0.5f * v1 * (1.f + erff(v1 * 0.70710678118654752f));
                    __half2 hp = __floats2half2_rn(v0, v1);
                    *(uint32_t*)(Ch + off) = *(uint32_t*)&hp;
                }
            }
        }
}

// ---------------- weight transpose+split (bf16 hi/lo) ----------------------
__global__ void __launch_bounds__(256) wconv_kernel(
    const float* __restrict__ W, bf16* __restrict__ hi, bf16* __restrict__ lo,
    int K, int N)
{
    __shared__ float tile[32][33];
    int k0 = blockIdx.y * 32, n0 = blockIdx.x * 32;
    int tx = threadIdx.x & 31, ty = threadIdx.x >> 5;
#pragma unroll
    for (int i = ty; i < 32; i += 8)
        tile[i][tx] = W[(size_t)(k0 + i) * N + n0 + tx];
    __syncthreads();
#pragma unroll
    for (int i = ty; i < 32; i += 8) {
        float v = tile[tx][i];
        bf16 h, l;
        split_bf16(v, h, l);
        size_t off = (size_t)(n0 + i) * K + k0 + tx;
        hi[off] = h; lo[off] = l;
    }
}

// ---------------- weight transpose (single fp16) ---------------------------
__global__ void __launch_bounds__(256) wconv_h_kernel(
    const float* __restrict__ W, __half* __restrict__ out, int K, int N)
{
    __shared__ float tile[32][33];
    int k0 = blockIdx.y * 32, n0 = blockIdx.x * 32;
    int tx = threadIdx.x & 31, ty = threadIdx.x >> 5;
#pragma unroll
    for (int i = ty; i < 32; i += 8)
        tile[i][tx] = W[(size_t)(k0 + i) * N + n0 + tx];
    __syncthreads();
#pragma unroll
    for (int i = ty; i < 32; i += 8)
        out[(size_t)(n0 + i) * K + k0 + tx] = __float2half(tile[tx][i]);
}

// ---------------- LayerNorm -> split bf16 ----------------------------------
__global__ void __launch_bounds__(256) ln_kernel(
    const float* __restrict__ x, const float* __restrict__ w,
    const float* __restrict__ b, bf16* __restrict__ out_hi, bf16* __restrict__ out_lo)
{
    int row = blockIdx.x;
    int t = threadIdx.x;
    const float* xr = x + (size_t)row * DQ;
    float v0[4];
    float s = 0.f, sq = 0.f;
#pragma unroll
    for (int i = 0; i < 4; i++) {
        float val = xr[t + i * 256];
        v0[i] = val; s += val; sq = fmaf(val, val, sq);
    }
    __shared__ float ss[8], ssq[8];
    __shared__ float mu_s, rs_s;
#pragma unroll
    for (int o = 16; o > 0; o >>= 1) {
        s  += __shfl_xor_sync(0xffffffffu, s, o);
        sq += __shfl_xor_sync(0xffffffffu, sq, o);
    }
    if ((t & 31) == 0) { ss[t >> 5] = s; ssq[t >> 5] = sq; }
    __syncthreads();
    if (t < 32) {
        float a  = (t < 8) ? ss[t]  : 0.f;
        float aq = (t < 8) ? ssq[t] : 0.f;
#pragma unroll
        for (int o = 4; o > 0; o >>= 1) {
            a  += __shfl_xor_sync(0xffffffffu, a, o);
            aq += __shfl_xor_sync(0xffffffffu, aq, o);
        }
        if (t == 0) {
            float mu = a * (1.f / DQ);
            float var = aq * (1.f / DQ) - mu * mu;
            mu_s = mu; rs_s = rsqrtf(var + 1e-5f);
        }
    }
    __syncthreads();
    float mu = mu_s, rs = rs_s;
#pragma unroll
    for (int i = 0; i < 4; i++) {
        int c = t + i * 256;
        float v = (v0[i] - mu) * rs * w[c] + b[c];
        bf16 h, l;
        split_bf16(v, h, l);
        out_hi[(size_t)row * DQ + c] = h;
        out_lo[(size_t)row * DQ + c] = l;
    }
}

// ---------------- LayerNorm -> single fp16 ---------------------------------
__global__ void __launch_bounds__(256) ln_kernel_h(
    const float* __restrict__ x, const float* __restrict__ w,
    const float* __restrict__ b, __half* __restrict__ out_h)
{
    int row = blockIdx.x;
    int t = threadIdx.x;
    const float* xr = x + (size_t)row * DQ;
    float v0[4];
    float s = 0.f, sq = 0.f;
#pragma unroll
    for (int i = 0; i < 4; i++) {
        float val = xr[t + i * 256];
        v0[i] = val; s += val; sq = fmaf(val, val, sq);
    }
    __shared__ float ss[8], ssq[8];
    __shared__ float mu_s, rs_s;
#pragma unroll
    for (int o = 16; o > 0; o >>= 1) {
        s  += __shfl_xor_sync(0xffffffffu, s, o);
        sq += __shfl_xor_sync(0xffffffffu, sq, o);
    }
    if ((t & 31) == 0) { ss[t >> 5] = s; ssq[t >> 5] = sq; }
    __syncthreads();
    if (t < 32) {
        float a  = (t < 8) ? ss[t]  : 0.f;
        float aq = (t < 8) ? ssq[t] : 0.f;
#pragma unroll
        for (int o = 4; o > 0; o >>= 1) {
            a  += __shfl_xor_sync(0xffffffffu, a, o);
            aq += __shfl_xor_sync(0xffffffffu, aq, o);
        }
        if (t == 0) {
            float mu = a * (1.f / DQ);
            float var = aq * (1.f / DQ) - mu * mu;
            mu_s = mu; rs_s = rsqrtf(var + 1e-5f);
        }
    }
    __syncthreads();
    float mu = mu_s, rs = rs_s;
#pragma unroll
    for (int i = 0; i < 4; i++) {
        int c = t + i * 256;
        float v = (v0[i] - mu) * rs * w[c] + b[c];
        out_h[(size_t)row * DQ + c] = __float2half(v);
    }
}

// ------------- performer feature map -> bf16 -------------------------------
__global__ void __launch_bounds__(256) feature_kernel(
    const float* __restrict__ src, const float* __restrict__ proj,
    bf16* __restrict__ dst)
{
    int bh = blockIdx.y;
    int h = bh & (HQ - 1), b = bh >> 4;
    int l0 = blockIdx.x * 64;
    __shared__ float data[64][HDQ + 1];
    __shared__ float pt[64][HDQ + 1];
    __shared__ float sqs[64];
    const float scale = 0.35355339059327373f;
    int tid = threadIdx.x;

    for (int idx = tid; idx < 64 * 64; idx += 256) {
        int t = idx >> 6, d = idx & 63;
        data[t][d] = src[(size_t)(b * LQ + l0 + t) * DQ + h * HDQ + d] * scale;
    }
    __syncthreads();
    if (tid < 64) {
        float s = 0.f;
#pragma unroll 8
        for (int d = 0; d < 64; d++) { float v = data[tid][d]; s = fmaf(v, v, s); }
        sqs[tid] = 0.5f * s;
    }

    int tt = (tid >> 4) << 2;
    int mm = (tid & 15) << 2;

    for (int mt = 0; mt < MQ; mt += 64) {
        __syncthreads();
        for (int idx = tid; idx < 64 * 64; idx += 256) {
            int m = idx >> 6, d = idx & 63;
            pt[m][d] = proj[(size_t)(mt + m) * HDQ + d];
        }
        __syncthreads();
        float acc[4][4];
#pragma unroll
        for (int i = 0; i < 4; i++)
#pragma unroll
            for (int j = 0; j < 4; j++) acc[i][j] = 0.f;
        for (int d = 0; d < 64; d++) {
            float a[4], bb[4];
#pragma unroll
            for (int i = 0; i < 4; i++) a[i] = data[tt + i][d];
#pragma unroll
            for (int j = 0; j < 4; j++) bb[j] = pt[mm + j][d];
#pragma unroll
            for (int i = 0; i < 4; i++)
#pragma unroll
                for (int j = 0; j < 4; j++)
                    acc[i][j] = fmaf(a[i], bb[j], acc[i][j]);
        }
#pragma unroll
        for (int i = 0; i < 4; i++) {
            float sv = sqs[tt + i];
            size_t orow = ((size_t)bh * LQ + l0 + tt + i) * MQ + mt + mm;
            float e0 = expf(acc[i][0] - sv + 1e-6f);
            float e1 = expf(acc[i][1] - sv + 1e-6f);
            float e2 = expf(acc[i][2] - sv + 1e-6f);
            float e3 = expf(acc[i][3] - sv + 1e-6f);
            uint2 o;
            o.x = packbf2(e0, e1);
            o.y = packbf2(e2, e3);
            *(uint2*)(dst + orow) = o;
        }
    }
}

// ---------------- kv = k_p^T @ v + k_sum (split-K atomics; bf16 kp) --------
__global__ void __launch_bounds__(256) kv_kernel(
    const bf16* __restrict__ kp, const float* __restrict__ v)
{
    const int SPL = 8;
    int bh = blockIdx.y;
    int h = bh & (HQ - 1), b = bh >> 4;
    int lbase = blockIdx.x * (LQ / SPL);
    __shared__ float kps[16][MQ];
    __shared__ float vs[16][HDQ + 4];
    int tid = threadIdx.x;
    int mi = (tid >> 3) << 3;
    int di = (tid & 7) << 3;
    float acc[8][8];
    float ks[8];
#pragma unroll
    for (int i = 0; i < 8; i++) {
        ks[i] = 0.f;
#pragma unroll
        for (int j = 0; j < 8; j++) acc[i][j] = 0.f;
    }
    bool owner = ((tid & 7) == 0);

    for (int lc = 0; lc < LQ / SPL; lc += 16) {
        // kp tile: 16 rows x 256 m in bf16 -> 512 chunks of 8
        for (int idx = tid; idx < 16 * 32; idx += 256) {
            int l = idx >> 5, m8 = (idx & 31) * 8;
            uint4 r = *(const uint4*)(kp + ((size_t)bh * LQ + lbase + lc + l) * MQ + m8);
            const __nv_bfloat162* p2 = (const __nv_bfloat162*)&r;
#pragma unroll
            for (int q = 0; q < 4; q++) {
                float2 f = __bfloat1622float2(p2[q]);
                kps[l][m8 + q * 2 + 0] = f.x;
                kps[l][m8 + q * 2 + 1] = f.y;
            }
        }
        for (int idx = tid; idx < 16 * 16; idx += 256) {
            int l = idx >> 4, d4 = (idx & 15) * 4;
            *(float4*)&vs[l][d4] =
                *(const float4*)(v + (size_t)(b * LQ + lbase + lc + l) * DQ + h * HDQ + d4);
        }
        __syncthreads();
#pragma unroll
        for (int l = 0; l < 16; l++) {
            float a[8], bb[8];
#pragma unroll
            for (int i = 0; i < 8; i++) a[i] = kps[l][mi + i];
#pragma unroll
            for (int j = 0; j < 8; j++) bb[j] = vs[l][di + j];
#pragma unroll
            for (int i = 0; i < 8; i++)
#pragma unroll
                for (int j = 0; j < 8; j++)
                    acc[i][j] = fmaf(a[i], bb[j], acc[i][j]);
            if (owner)
#pragma unroll
                for (int i = 0; i < 8; i++) ks[i] += a[i];
        }
        __syncthreads();
    }
#pragma unroll
    for (int i = 0; i < 8; i++)
#pragma unroll
        for (int j = 0; j < 8; j++)
            atomicAdd(&g_kv[((size_t)bh * MQ + mi + i) * HDQ + di + j], acc[i][j]);
    if (owner)
#pragma unroll
        for (int i = 0; i < 8; i++)
            atomicAdd(&g_ksum[bh * MQ + mi + i], ks[i]);
}

// ---------------- z (bf16 qp) ----------------
__global__ void __launch_bounds__(256) z_kernel(const bf16* __restrict__ qp)
{
    int row = blockIdx.x * 8 + (threadIdx.x >> 5);
    int lane = threadIdx.x & 31;
    int bh = row >> 12;
    const bf16* qr = qp + (size_t)row * MQ;
    const float* kss = g_ksum + bh * MQ;
    float s = 0.f;
#pragma unroll
    for (int m0 = 0; m0 < MQ; m0 += 64) {
        int m = m0 + lane * 2;
        __nv_bfloat162 q2 = *(const __nv_bfloat162*)(qr + m);
        float2 f = __bfloat1622float2(q2);
        s = fmaf(f.x, kss[m], s);
        s = fmaf(f.y, kss[m + 1], s);
    }
#pragma unroll
    for (int o = 16; o > 0; o >>= 1) s += __shfl_xor_sync(0xffffffffu, s, o);
    if (lane == 0) g_z[row] = 1.f / (s + 1e-6f);
}

// ---------------- attn combine (bf16 qp) -> split bf16 ---------------------
__global__ void __launch_bounds__(256) attn_kernel(
    const bf16* __restrict__ qp, bf16* __restrict__ out_hi, bf16* __restrict__ out_lo)
{
    int bh = blockIdx.y;
    int h = bh & (HQ - 1), b = bh >> 4;
    int l0 = blockIdx.x * 128;
    __shared__ float qs[128][36];
    __shared__ float kvs[32][HDQ + 4];
    int tid = threadIdx.x;
    int ti = (tid >> 3) << 2;
    int di = (tid & 7) << 3;
    float acc[4][8];
#pragma unroll
    for (int i = 0; i < 4; i++)
#pragma unroll
        for (int j = 0; j < 8; j++) acc[i][j] = 0.f;

    for (int m0 = 0; m0 < MQ; m0 += 32) {
        // qp tile: 128 rows x 32 m bf16 -> 512 chunks of 8
        for (int idx = tid; idx < 128 * 4; idx += 256) {
            int t = idx >> 2, mq = (idx & 3) * 8;
            uint4 r = *(const uint4*)(qp + ((size_t)bh * LQ + l0 + t) * MQ + m0 + mq);
            const __nv_bfloat162* p2 = (const __nv_bfloat162*)&r;
#pragma unroll
            for (int q = 0; q < 4; q++) {
                float2 f = __bfloat1622float2(p2[q]);
                qs[t][mq + q * 2 + 0] = f.x;
                qs[t][mq + q * 2 + 1] = f.y;
            }
        }
        for (int idx = tid; idx < 32 * 16; idx += 256) {
            int m = idx >> 4, dq = (idx & 15) * 4;
            *(float4*)&kvs[m][dq] =
                *(const float4*)(&g_kv[((size_t)bh * MQ + m0 + m) * HDQ + dq]);
        }
        __syncthreads();
#pragma unroll 4
        for (int m = 0; m < 32; m++) {
            float a[4], bb[8];
#pragma unroll
            for (int i = 0; i < 4; i++) a[i] = qs[ti + i][m];
#pragma unroll
            for (int j = 0; j < 8; j++) bb[j] = kvs[m][di + j];
#pragma unroll
            for (int i = 0; i < 4; i++)
#pragma unroll
                for (int j = 0; j < 8; j++)
                    acc[i][j] = fmaf(a[i], bb[j], acc[i][j]);
        }
        __syncthreads();
    }
#pragma unroll
    for (int i = 0; i < 4; i++) {
        float zz = g_z[bh * LQ + l0 + ti + i];
        size_t token = (size_t)(b * LQ + l0 + ti + i);
        size_t base = token * DQ + h * HDQ + di;
#pragma unroll
        for (int j = 0; j < 8; j += 2) {
            float v0 = acc[i][j] * zz, v1 = acc[i][j + 1] * zz;
            bf16 h0, l0b, h1, l1;
            split_bf16(v0, h0, l0b);
            split_bf16(v1, h1, l1);
            *(uint32_t*)(out_hi + base + j) =
                (uint32_t)__bfloat16_as_ushort(h0) | ((uint32_t)__bfloat16_as_ushort(h1) << 16);
            *(uint32_t*)(out_lo + base + j) =
                (uint32_t)__bfloat16_as_ushort(l0b) | ((uint32_t)__bfloat16_as_ushort(l1) << 16);
        }
    }
}

// ---------------------------------------------------------------------------
extern "C" void kernel_launch(void* const* d_in, const int* in_sizes, int n_in,
                              void* d_out, int out_size)
{
    const float* x     = (const float*)d_in[0];
    const float* ln1_w = (const float*)d_in[1];
    const float* ln1_b = (const float*)d_in[2];
    const float* ln2_w = (const float*)d_in[3];
    const float* ln2_b = (const float*)d_in[4];
    const float* Wq    = (const float*)d_in[5];
    const float* bq    = (const float*)d_in[6];
    const float* Wk    = (const float*)d_in[7];
    const float* bk    = (const float*)d_in[8];
    const float* Wv    = (const float*)d_in[9];
    const float* bv    = (const float*)d_in[10];
    const float* Wo    = (const float*)d_in[11];
    const float* bo    = (const float*)d_in[12];
    const float* W1    = (const float*)d_in[13];
    const float* b1    = (const float*)d_in[14];
    const float* W2    = (const float*)d_in[15];
    const float* b2    = (const float*)d_in[16];
    const float* proj  = (const float*)d_in[17];
    float* out = (float*)d_out;

    float *p_q, *p_k, *p_v, *p_kv, *p_ksum, *p_x2;
    bf16 *p_qp, *p_kp;
    bf16 *p_hh, *p_hl, *p_ah, *p_al;
    __half *p_h2, *p_midh, *p_w1h, *p_w2h;
    bf16 *p_wq_h, *p_wq_l, *p_wk_h, *p_wk_l, *p_wv_h, *p_wv_l, *p_wo_h, *p_wo_l;
    cudaGetSymbolAddress((void**)&p_q,    g_q);
    cudaGetSymbolAddress((void**)&p_k,    g_k);
    cudaGetSymbolAddress((void**)&p_v,    g_v);
    cudaGetSymbolAddress((void**)&p_qp,   g_qp);
    cudaGetSymbolAddress((void**)&p_kp,   g_kp);
    cudaGetSymbolAddress((void**)&p_kv,   g_kv);
    cudaGetSymbolAddress((void**)&p_ksum, g_ksum);
    cudaGetSymbolAddress((void**)&p_x2,   g_x2);
    cudaGetSymbolAddress((void**)&p_hh,   g_h_hi);
    cudaGetSymbolAddress((void**)&p_hl,   g_h_lo);
    cudaGetSymbolAddress((void**)&p_ah,   g_attn_hi);
    cudaGetSymbolAddress((void**)&p_al,   g_attn_lo);
    cudaGetSymbolAddress((void**)&p_h2,   g_h2);
    cudaGetSymbolAddress((void**)&p_midh, g_midh);
    cudaGetSymbolAddress((void**)&p_w1h,  g_w1h);
    cudaGetSymbolAddress((void**)&p_w2h,  g_w2h);
    cudaGetSymbolAddress((void**)&p_wq_h, g_wq_hi); cudaGetSymbolAddress((void**)&p_wq_l, g_wq_lo);
    cudaGetSymbolAddress((void**)&p_wk_h, g_wk_hi); cudaGetSymbolAddress((void**)&p_wk_l, g_wk_lo);
    cudaGetSymbolAddress((void**)&p_wv_h, g_wv_hi); cudaGetSymbolAddress((void**)&p_wv_l, g_wv_lo);
    cudaGetSymbolAddress((void**)&p_wo_h, g_wo_hi); cudaGetSymbolAddress((void**)&p_wo_l, g_wo_lo);

    const int SMEM_GEMM = 2 * STAGE_B;      // 80KB
    const int SMEM_H    = 2 * HSTAGE_B;     // 40KB
    cudaFuncSetAttribute(tc_gemm2<0>, cudaFuncAttributeMaxDynamicSharedMemorySize, SMEM_GEMM);
    cudaFuncSetAttribute(tc_gemm2<1>, cudaFuncAttributeMaxDynamicSharedMemorySize, SMEM_GEMM);
    cudaFuncSetAttribute(tc_gemm_h<1>, cudaFuncAttributeMaxDynamicSharedMemorySize, SMEM_H);
    cudaFuncSetAttribute(tc_gemm_h<2>, cudaFuncAttributeMaxDynamicSharedMemorySize, SMEM_H);

    dim3 gD(DQ / 128, NTOK / 128);
    dim3 g4D(4 * DQ / 128, NTOK / 128);

    // weight conversions
    wconv_kernel<<<dim3(DQ / 32, DQ / 32), 256>>>(Wq, p_wq_h, p_wq_l, DQ, DQ);
    wconv_kernel<<<dim3(DQ / 32, DQ / 32), 256>>>(Wk, p_wk_h, p_wk_l, DQ, DQ);
    wconv_kernel<<<dim3(DQ / 32, DQ / 32), 256>>>(Wv, p_wv_h, p_wv_l, DQ, DQ);
    wconv_kernel<<<dim3(DQ / 32, DQ / 32), 256>>>(Wo, p_wo_h, p_wo_l, DQ, DQ);
    wconv_h_kernel<<<dim3(4 * DQ / 32, DQ / 32), 256>>>(W1, p_w1h, DQ, 4 * DQ);
    wconv_h_kernel<<<dim3(DQ / 32, 4 * DQ / 32), 256>>>(W2, p_w2h, 4 * DQ, DQ);

    // LN1 -> split h
    ln_kernel<<<NTOK, 256>>>(x, ln1_w, ln1_b, p_hh, p_hl);
    // QKV (bf16 3-term)
    tc_gemm2<0><<<gD, 256, SMEM_GEMM>>>(p_hh, p_hl, p_wq_h, p_wq_l, bq, nullptr, p_q, DQ, DQ);
    tc_gemm2<0><<<gD, 256, SMEM_GEMM>>>(p_hh, p_hl, p_wk_h, p_wk_l, bk, nullptr, p_k, DQ, DQ);
    tc_gemm2<0><<<gD, 256, SMEM_GEMM>>>(p_hh, p_hl, p_wv_h, p_wv_l, bv, nullptr, p_v, DQ, DQ);
    // performer feature maps -> bf16
    feature_kernel<<<dim3(LQ / 64, NH), 256>>>(p_q, proj, p_qp);
    feature_kernel<<<dim3(LQ / 64, NH), 256>>>(p_k, proj, p_kp);
    // kv + k_sum
    cudaMemsetAsync(p_kv,   0, (size_t)NH * MQ * HDQ * sizeof(float));
    cudaMemsetAsync(p_ksum, 0, (size_t)NH * MQ * sizeof(float));
    kv_kernel<<<dim3(8, NH), 256>>>(p_kp, p_v);
    // normalizer z
    z_kernel<<<NH * LQ / 8, 256>>>(p_qp);
    // attention combine -> split attn
    attn_kernel<<<dim3(LQ / 128, NH), 256>>>(p_qp, p_ah, p_al);
    // output proj + residual (bf16 3-term)
    tc_gemm2<1><<<gD, 256, SMEM_GEMM>>>(p_ah, p_al, p_wo_h, p_wo_l, bo, x, p_x2, DQ, DQ);
    // LN2 -> single fp16
    ln_kernel_h<<<NTOK, 256>>>(p_x2, ln2_w, ln2_b, p_h2);
    // MLP up + gelu (fp16 single) -> fp16 mid
    tc_gemm_h<2><<<g4D, 256, SMEM_H>>>(p_h2, p_w1h, b1, nullptr, nullptr, p_midh, 4 * DQ, DQ);
    // MLP down + residual (fp16 single) -> out
    tc_gemm_h<1><<<gD, 256, SMEM_H>>>(p_midh, p_w2h, b2, p_x2, out, nullptr, DQ, 4 * DQ);
}

// round 17
// speedup vs baseline: 1.0482x; 1.0025x over previous
#include <cuda_runtime.h>
#include <cuda_bf16.h>
#include <cuda_fp16.h>
#include <math.h>
#include <stdint.h>

// Problem constants
#define BQ   4
#define LQ   4096
#define DQ   1024
#define HQ   16
#define HDQ  64
#define MQ   256
#define NTOK (BQ * LQ)   // 16384
#define NH   (BQ * HQ)   // 64

typedef __nv_bfloat16 bf16;

// ---------------- scratch (device globals; no runtime allocation) ----------
__device__ float g_q   [NTOK * DQ];
__device__ float g_k   [NTOK * DQ];
__device__ float g_v   [NTOK * DQ];
__device__ bf16  g_qp  [NH * LQ * MQ];   // bf16 features (128 MB)
__device__ bf16  g_kp  [NH * LQ * MQ];
__device__ float g_kv  [NH * MQ * HDQ];
__device__ float g_ksum[NH * MQ];
__device__ float g_z   [NH * LQ];
__device__ float g_x2  [NTOK * DQ];

// split-bf16 activations (attention path, 3-term)
__device__ bf16 g_h_hi   [NTOK * DQ];
__device__ bf16 g_h_lo   [NTOK * DQ];
__device__ bf16 g_attn_hi[NTOK * DQ];
__device__ bf16 g_attn_lo[NTOK * DQ];

// single-fp16 activations (MLP path)
__device__ __half g_h2   [NTOK * DQ];
__device__ __half g_midh [NTOK * 4 * DQ];

// split-bf16 transposed weights [N,K] (attention path)
__device__ bf16 g_wq_hi[DQ * DQ], g_wq_lo[DQ * DQ];
__device__ bf16 g_wk_hi[DQ * DQ], g_wk_lo[DQ * DQ];
__device__ bf16 g_wv_hi[DQ * DQ], g_wv_lo[DQ * DQ];
__device__ bf16 g_wo_hi[DQ * DQ], g_wo_lo[DQ * DQ];
// single-fp16 transposed weights [N,K] (MLP path)
__device__ __half g_w1h[DQ * 4 * DQ];
__device__ __half g_w2h[4 * DQ * DQ];

// ======================= PTX helpers =======================================
__device__ __forceinline__ uint32_t smem_u32(const void* p) {
    uint32_t a;
    asm("{ .reg .u64 t; cvta.to.shared.u64 t, %1; cvt.u32.u64 %0, t; }" : "=r"(a) : "l"(p));
    return a;
}
__device__ __forceinline__ void ldsm4(uint32_t* r, uint32_t addr) {
    asm volatile("ldmatrix.sync.aligned.m8n8.x4.shared.b16 {%0,%1,%2,%3}, [%4];"
        : "=r"(r[0]), "=r"(r[1]), "=r"(r[2]), "=r"(r[3]) : "r"(addr));
}
__device__ __forceinline__ void mma16816(float* d, const uint32_t* a, const uint32_t* b) {
    asm volatile(
        "mma.sync.aligned.m16n8k16.row.col.f32.bf16.bf16.f32 "
        "{%0,%1,%2,%3}, {%4,%5,%6,%7}, {%8,%9}, {%0,%1,%2,%3};"
        : "+f"(d[0]), "+f"(d[1]), "+f"(d[2]), "+f"(d[3])
        : "r"(a[0]), "r"(a[1]), "r"(a[2]), "r"(a[3]), "r"(b[0]), "r"(b[1]));
}
__device__ __forceinline__ void mma16816h(float* d, const uint32_t* a, const uint32_t* b) {
    asm volatile(
        "mma.sync.aligned.m16n8k16.row.col.f32.f16.f16.f32 "
        "{%0,%1,%2,%3}, {%4,%5,%6,%7}, {%8,%9}, {%0,%1,%2,%3};"
        : "+f"(d[0]), "+f"(d[1]), "+f"(d[2]), "+f"(d[3])
        : "r"(a[0]), "r"(a[1]), "r"(a[2]), "r"(a[3]), "r"(b[0]), "r"(b[1]));
}
#define CP_ASYNC16(dst, src) \
    asm volatile("cp.async.cg.shared.global [%0], [%1], 16;" :: "r"(dst), "l"(src))
#define CP_COMMIT() asm volatile("cp.async.commit_group;" ::: "memory")
#define CP_WAIT1()  asm volatile("cp.async.wait_group 1;" ::: "memory")
#define CP_WAIT0()  asm volatile("cp.async.wait_group 0;" ::: "memory")

__device__ __forceinline__ void split_bf16(float v, bf16& hi, bf16& lo) {
    hi = __float2bfloat16(v);
    lo = __float2bfloat16(v - __bfloat162float(hi));
}
__device__ __forceinline__ uint32_t packbf2(float a, float b) {
    __nv_bfloat162 t = __floats2bfloat162_rn(a, b);
    return *reinterpret_cast<uint32_t*>(&t);
}

// ============ tensor-core GEMM v2: pre-split bf16 operands (3-term) ========
#define PAD    40
#define ARR_B  10240u
#define STAGE_B (4 * ARR_B)

__device__ __forceinline__ void load_stage(
    uint32_t sbase, const bf16* Ahi, const bf16* Alo,
    const bf16* Bhi, const bf16* Blo,
    int m0, int n0, int kt, int K, int tid)
{
#pragma unroll
    for (int half = 0; half < 2; half++) {
        int c = tid + half * 256;
        int row = c >> 2, kc = (c & 3) * 8;
        uint32_t dst = sbase + (uint32_t)(row * PAD + kc) * 2;
        size_t aoff = (size_t)(m0 + row) * K + kt + kc;
        size_t boff = (size_t)(n0 + row) * K + kt + kc;
        CP_ASYNC16(dst,              Ahi + aoff);
        CP_ASYNC16(dst + ARR_B,      Alo + aoff);
        CP_ASYNC16(dst + 2 * ARR_B,  Bhi + boff);
        CP_ASYNC16(dst + 3 * ARR_B,  Blo + boff);
    }
}

template <int MODE>   // 0: +bias -> fp32   1: +bias+res -> fp32
__global__ void __launch_bounds__(256, 2) tc_gemm2(
    const bf16* __restrict__ Ahi, const bf16* __restrict__ Alo,
    const bf16* __restrict__ Bhi, const bf16* __restrict__ Blo,
    const float* __restrict__ bias, const float* __restrict__ res,
    float* __restrict__ C, int N, int K)
{
    extern __shared__ __align__(16) char smem[];
    uint32_t sb = smem_u32(smem);

    int tid = threadIdx.x, wid = tid >> 5, lane = tid & 31;
    int m0 = blockIdx.y * 128, n0 = blockIdx.x * 128;
    int m0w = (wid & 1) * 64;
    int n0w = (wid >> 1) * 32;

    float acc[4][4][4];
#pragma unroll
    for (int i = 0; i < 4; i++)
#pragma unroll
        for (int j = 0; j < 4; j++)
#pragma unroll
            for (int q = 0; q < 4; q++) acc[i][j][q] = 0.f;

    int aRowOff = ((lane >> 3) & 1) * 8 + (lane & 7);
    int aKOff   = (lane >> 4) * 8;
    int bNOff   = (lane >> 4) * 8 + (lane & 7);
    int bKOff   = ((lane >> 3) & 1) * 8;

    int KT = K / 32;
    load_stage(sb, Ahi, Alo, Bhi, Blo, m0, n0, 0, K, tid);
    CP_COMMIT();

    for (int kt = 0; kt < KT; kt++) {
        if (kt + 1 < KT) {
            load_stage(sb + ((kt + 1) & 1) * STAGE_B, Ahi, Alo, Bhi, Blo,
                       m0, n0, (kt + 1) * 32, K, tid);
            CP_COMMIT();
            CP_WAIT1();
        } else {
            CP_WAIT0();
        }
        __syncthreads();

        uint32_t st = sb + (kt & 1) * STAGE_B;
#pragma unroll
        for (int ks = 0; ks < 32; ks += 16) {
            uint32_t Ah[4][4], Al[4][4], Bh[2][4], Bl[2][4];
#pragma unroll
            for (int mi = 0; mi < 4; mi++) {
                uint32_t off = (uint32_t)((m0w + mi * 16 + aRowOff) * PAD + ks + aKOff) * 2;
                ldsm4(Ah[mi], st + off);
                ldsm4(Al[mi], st + ARR_B + off);
            }
#pragma unroll
            for (int np = 0; np < 2; np++) {
                uint32_t off = (uint32_t)((n0w + np * 16 + bNOff) * PAD + ks + bKOff) * 2;
                ldsm4(Bh[np], st + 2 * ARR_B + off);
                ldsm4(Bl[np], st + 3 * ARR_B + off);
            }
#pragma unroll
            for (int mi = 0; mi < 4; mi++)
#pragma unroll
                for (int ni = 0; ni < 4; ni++) {
                    const uint32_t* bh = &Bh[ni >> 1][(ni & 1) * 2];
                    const uint32_t* bl = &Bl[ni >> 1][(ni & 1) * 2];
                    mma16816(acc[mi][ni], Ah[mi], bh);
                    mma16816(acc[mi][ni], Al[mi], bh);
                    mma16816(acc[mi][ni], Ah[mi], bl);
                }
        }
        __syncthreads();
    }

    int rOff = lane >> 2;
    int cOff = (lane & 3) * 2;
#pragma unroll
    for (int mi = 0; mi < 4; mi++)
#pragma unroll
        for (int ni = 0; ni < 4; ni++) {
            int col = n0 + n0w + ni * 8 + cOff;
            float b0 = bias[col], b1 = bias[col + 1];
#pragma unroll
            for (int half = 0; half < 2; half++) {
                int row = m0 + m0w + mi * 16 + rOff + half * 8;
                size_t off = (size_t)row * N + col;
                float v0 = acc[mi][ni][half * 2 + 0] + b0;
                float v1 = acc[mi][ni][half * 2 + 1] + b1;
                if (MODE == 1) { v0 += res[off]; v1 += res[off + 1]; }
                float2 o; o.x = v0; o.y = v1;
                *(float2*)(C + off) = o;
            }
        }
}

// ============ tc_gemm_h: single-fp16 operands (MLP path) ===================
#define HSTAGE_B (2 * ARR_B)

__device__ __forceinline__ void load_stage_h(
    uint32_t sbase, const __half* A, const __half* B,
    int m0, int n0, int kt, int K, int tid)
{
#pragma unroll
    for (int half = 0; half < 2; half++) {
        int c = tid + half * 256;
        int row = c >> 2, kc = (c & 3) * 8;
        uint32_t dst = sbase + (uint32_t)(row * PAD + kc) * 2;
        size_t aoff = (size_t)(m0 + row) * K + kt + kc;
        size_t boff = (size_t)(n0 + row) * K + kt + kc;
        CP_ASYNC16(dst,         A + aoff);
        CP_ASYNC16(dst + ARR_B, B + boff);
    }
}

template <int MODE>   // 1: +bias+res -> fp32 C   2: gelu(+bias) -> fp16 Ch
__global__ void __launch_bounds__(256, 2) tc_gemm_h(
    const __half* __restrict__ A, const __half* __restrict__ B,
    const float* __restrict__ bias, const float* __restrict__ res,
    float* __restrict__ C, __half* __restrict__ Ch,
    int N, int K)
{
    extern __shared__ __align__(16) char smem[];
    uint32_t sb = smem_u32(smem);

    int tid = threadIdx.x, wid = tid >> 5, lane = tid & 31;
    int m0 = blockIdx.y * 128, n0 = blockIdx.x * 128;
    int m0w = (wid & 1) * 64;
    int n0w = (wid >> 1) * 32;

    float acc[4][4][4];
#pragma unroll
    for (int i = 0; i < 4; i++)
#pragma unroll
        for (int j = 0; j < 4; j++)
#pragma unroll
            for (int q = 0; q < 4; q++) acc[i][j][q] = 0.f;

    int aRowOff = ((lane >> 3) & 1) * 8 + (lane & 7);
    int aKOff   = (lane >> 4) * 8;
    int bNOff   = (lane >> 4) * 8 + (lane & 7);
    int bKOff   = ((lane >> 3) & 1) * 8;

    int KT = K / 32;
    load_stage_h(sb, A, B, m0, n0, 0, K, tid);
    CP_COMMIT();

    for (int kt = 0; kt < KT; kt++) {
        if (kt + 1 < KT) {
            load_stage_h(sb + ((kt + 1) & 1) * HSTAGE_B, A, B,
                         m0, n0, (kt + 1) * 32, K, tid);
            CP_COMMIT();
            CP_WAIT1();
        } else {
            CP_WAIT0();
        }
        __syncthreads();

        uint32_t st = sb + (kt & 1) * HSTAGE_B;
#pragma unroll
        for (int ks = 0; ks < 32; ks += 16) {
            uint32_t Af[4][4], Bf[2][4];
#pragma unroll
            for (int mi = 0; mi < 4; mi++) {
                uint32_t off = (uint32_t)((m0w + mi * 16 + aRowOff) * PAD + ks + aKOff) * 2;
                ldsm4(Af[mi], st + off);
            }
#pragma unroll
            for (int np = 0; np < 2; np++) {
                uint32_t off = (uint32_t)((n0w + np * 16 + bNOff) * PAD + ks + bKOff) * 2;
                ldsm4(Bf[np], st + ARR_B + off);
            }
#pragma unroll
            for (int mi = 0; mi < 4; mi++)
#pragma unroll
                for (int ni = 0; ni < 4; ni++)
                    mma16816h(acc[mi][ni], Af[mi], &Bf[ni >> 1][(ni & 1) * 2]);
        }
        __syncthreads();
    }

    int rOff = lane >> 2;
    int cOff = (lane & 3) * 2;
#pragma unroll
    for (int mi = 0; mi < 4; mi++)
#pragma unroll
        for (int ni = 0; ni < 4; ni++) {
            int col = n0 + n0w + ni * 8 + cOff;
            float b0 = bias[col], b1 = bias[col + 1];
#pragma unroll
            for (int half = 0; half < 2; half++) {
                int row = m0 + m0w + mi * 16 + rOff + half * 8;
                size_t off = (size_t)row * N + col;
                float v0 = acc[mi][ni][half * 2 + 0] + b0;
                float v1 = acc[mi][ni][half * 2 + 1] + b1;
                if (MODE == 1) {
                    v0 += res[off]; v1 += res[off + 1];
                    float2 o; o.x = v0; o.y = v1;
                    *(float2*)(C + off) = o;
                } else {
                    v0 = 0.5f * v0 * (1.f + erff(v0 * 0.70710678118654752f));
                    v1 = 0.5f * v1 * (1.f + erff(v1 * 0.70710678118654752f));
                    __half2 hp = __floats2half2_rn(v0, v1);
                    *(uint32_t*)(Ch + off) = *(uint32_t*)&hp;
                }
            }
        }
}

// ---------------- weight transpose+split (bf16 hi/lo) ----------------------
__global__ void __launch_bounds__(256) wconv_kernel(
    const float* __restrict__ W, bf16* __restrict__ hi, bf16* __restrict__ lo,
    int K, int N)
{
    __shared__ float tile[32][33];
    int k0 = blockIdx.y * 32, n0 = blockIdx.x * 32;
    int tx = threadIdx.x & 31, ty = threadIdx.x >> 5;
#pragma unroll
    for (int i = ty; i < 32; i += 8)
        tile[i][tx] = W[(size_t)(k0 + i) * N + n0 + tx];
    __syncthreads();
#pragma unroll
    for (int i = ty; i < 32; i += 8) {
        float v = tile[tx][i];
        bf16 h, l;
        split_bf16(v, h, l);
        size_t off = (size_t)(n0 + i) * K + k0 + tx;
        hi[off] = h; lo[off] = l;
    }
}

// ---------------- weight transpose (single fp16) ---------------------------
__global__ void __launch_bounds__(256) wconv_h_kernel(
    const float* __restrict__ W, __half* __restrict__ out, int K, int N)
{
    __shared__ float tile[32][33];
    int k0 = blockIdx.y * 32, n0 = blockIdx.x * 32;
    int tx = threadIdx.x & 31, ty = threadIdx.x >> 5;
#pragma unroll
    for (int i = ty; i < 32; i += 8)
        tile[i][tx] = W[(size_t)(k0 + i) * N + n0 + tx];
    __syncthreads();
#pragma unroll
    for (int i = ty; i < 32; i += 8)
        out[(size_t)(n0 + i) * K + k0 + tx] = __float2half(tile[tx][i]);
}

// ---------------- LayerNorm -> split bf16 ----------------------------------
__global__ void __launch_bounds__(256) ln_kernel(
    const float* __restrict__ x, const float* __restrict__ w,
    const float* __restrict__ b, bf16* __restrict__ out_hi, bf16* __restrict__ out_lo)
{
    int row = blockIdx.x;
    int t = threadIdx.x;
    const float* xr = x + (size_t)row * DQ;
    float v0[4];
    float s = 0.f, sq = 0.f;
#pragma unroll
    for (int i = 0; i < 4; i++) {
        float val = xr[t + i * 256];
        v0[i] = val; s += val; sq = fmaf(val, val, sq);
    }
    __shared__ float ss[8], ssq[8];
    __shared__ float mu_s, rs_s;
#pragma unroll
    for (int o = 16; o > 0; o >>= 1) {
        s  += __shfl_xor_sync(0xffffffffu, s, o);
        sq += __shfl_xor_sync(0xffffffffu, sq, o);
    }
    if ((t & 31) == 0) { ss[t >> 5] = s; ssq[t >> 5] = sq; }
    __syncthreads();
    if (t < 32) {
        float a  = (t < 8) ? ss[t]  : 0.f;
        float aq = (t < 8) ? ssq[t] : 0.f;
#pragma unroll
        for (int o = 4; o > 0; o >>= 1) {
            a  += __shfl_xor_sync(0xffffffffu, a, o);
            aq += __shfl_xor_sync(0xffffffffu, aq, o);
        }
        if (t == 0) {
            float mu = a * (1.f / DQ);
            float var = aq * (1.f / DQ) - mu * mu;
            mu_s = mu; rs_s = rsqrtf(var + 1e-5f);
        }
    }
    __syncthreads();
    float mu = mu_s, rs = rs_s;
#pragma unroll
    for (int i = 0; i < 4; i++) {
        int c = t + i * 256;
        float v = (v0[i] - mu) * rs * w[c] + b[c];
        bf16 h, l;
        split_bf16(v, h, l);
        out_hi[(size_t)row * DQ + c] = h;
        out_lo[(size_t)row * DQ + c] = l;
    }
}

// ---------------- LayerNorm -> single fp16 ---------------------------------
__global__ void __launch_bounds__(256) ln_kernel_h(
    const float* __restrict__ x, const float* __restrict__ w,
    const float* __restrict__ b, __half* __restrict__ out_h)
{
    int row = blockIdx.x;
    int t = threadIdx.x;
    const float* xr = x + (size_t)row * DQ;
    float v0[4];
    float s = 0.f, sq = 0.f;
#pragma unroll
    for (int i = 0; i < 4; i++) {
        float val = xr[t + i * 256];
        v0[i] = val; s += val; sq = fmaf(val, val, sq);
    }
    __shared__ float ss[8], ssq[8];
    __shared__ float mu_s, rs_s;
#pragma unroll
    for (int o = 16; o > 0; o >>= 1) {
        s  += __shfl_xor_sync(0xffffffffu, s, o);
        sq += __shfl_xor_sync(0xffffffffu, sq, o);
    }
    if ((t & 31) == 0) { ss[t >> 5] = s; ssq[t >> 5] = sq; }
    __syncthreads();
    if (t < 32) {
        float a  = (t < 8) ? ss[t]  : 0.f;
        float aq = (t < 8) ? ssq[t] : 0.f;
#pragma unroll
        for (int o = 4; o > 0; o >>= 1) {
            a  += __shfl_xor_sync(0xffffffffu, a, o);
            aq += __shfl_xor_sync(0xffffffffu, aq, o);
        }
        if (t == 0) {
            float mu = a * (1.f / DQ);
            float var = aq * (1.f / DQ) - mu * mu;
            mu_s = mu; rs_s = rsqrtf(var + 1e-5f);
        }
    }
    __syncthreads();
    float mu = mu_s, rs = rs_s;
#pragma unroll
    for (int i = 0; i < 4; i++) {
        int c = t + i * 256;
        float v = (v0[i] - mu) * rs * w[c] + b[c];
        out_h[(size_t)row * DQ + c] = __float2half(v);
    }
}

// ------------- performer feature map -> bf16 -------------------------------
__global__ void __launch_bounds__(256) feature_kernel(
    const float* __restrict__ src, const float* __restrict__ proj,
    bf16* __restrict__ dst)
{
    int bh = blockIdx.y;
    int h = bh & (HQ - 1), b = bh >> 4;
    int l0 = blockIdx.x * 64;
    __shared__ float data[64][HDQ + 1];
    __shared__ float pt[64][HDQ + 1];
    __shared__ float sqs[64];
    const float scale = 0.35355339059327373f;
    int tid = threadIdx.x;

    for (int idx = tid; idx < 64 * 64; idx += 256) {
        int t = idx >> 6, d = idx & 63;
        data[t][d] = src[(size_t)(b * LQ + l0 + t) * DQ + h * HDQ + d] * scale;
    }
    __syncthreads();
    if (tid < 64) {
        float s = 0.f;
#pragma unroll 8
        for (int d = 0; d < 64; d++) { float v = data[tid][d]; s = fmaf(v, v, s); }
        sqs[tid] = 0.5f * s;
    }

    int tt = (tid >> 4) << 2;
    int mm = (tid & 15) << 2;

    for (int mt = 0; mt < MQ; mt += 64) {
        __syncthreads();
        for (int idx = tid; idx < 64 * 64; idx += 256) {
            int m = idx >> 6, d = idx & 63;
            pt[m][d] = proj[(size_t)(mt + m) * HDQ + d];
        }
        __syncthreads();
        float acc[4][4];
#pragma unroll
        for (int i = 0; i < 4; i++)
#pragma unroll
            for (int j = 0; j < 4; j++) acc[i][j] = 0.f;
        for (int d = 0; d < 64; d++) {
            float a[4], bb[4];
#pragma unroll
            for (int i = 0; i < 4; i++) a[i] = data[tt + i][d];
#pragma unroll
            for (int j = 0; j < 4; j++) bb[j] = pt[mm + j][d];
#pragma unroll
            for (int i = 0; i < 4; i++)
#pragma unroll
                for (int j = 0; j < 4; j++)
                    acc[i][j] = fmaf(a[i], bb[j], acc[i][j]);
        }
#pragma unroll
        for (int i = 0; i < 4; i++) {
            float sv = sqs[tt + i];
            size_t orow = ((size_t)bh * LQ + l0 + tt + i) * MQ + mt + mm;
            float e0 = expf(acc[i][0] - sv + 1e-6f);
            float e1 = expf(acc[i][1] - sv + 1e-6f);
            float e2 = expf(acc[i][2] - sv + 1e-6f);
            float e3 = expf(acc[i][3] - sv + 1e-6f);
            uint2 o;
            o.x = packbf2(e0, e1);
            o.y = packbf2(e2, e3);
            *(uint2*)(dst + orow) = o;
        }
    }
}

// ---------------- kv = k_p^T @ v + k_sum (split-K atomics; bf16 kp) --------
__global__ void __launch_bounds__(256) kv_kernel(
    const bf16* __restrict__ kp, const float* __restrict__ v)
{
    const int SPL = 8;
    int bh = blockIdx.y;
    int h = bh & (HQ - 1), b = bh >> 4;
    int lbase = blockIdx.x * (LQ / SPL);
    __shared__ float kps[16][MQ];
    __shared__ float vs[16][HDQ + 4];
    int tid = threadIdx.x;
    int mi = (tid >> 3) << 3;
    int di = (tid & 7) << 3;
    float acc[8][8];
    float ks[8];
#pragma unroll
    for (int i = 0; i < 8; i++) {
        ks[i] = 0.f;
#pragma unroll
        for (int j = 0; j < 8; j++) acc[i][j] = 0.f;
    }
    bool owner = ((tid & 7) == 0);

    for (int lc = 0; lc < LQ / SPL; lc += 16) {
        // kp tile: 16 rows x 256 m in bf16 -> 512 chunks of 8
        for (int idx = tid; idx < 16 * 32; idx += 256) {
            int l = idx >> 5, m8 = (idx & 31) * 8;
            uint4 r = *(const uint4*)(kp + ((size_t)bh * LQ + lbase + lc + l) * MQ + m8);
            const __nv_bfloat162* p2 = (const __nv_bfloat162*)&r;
#pragma unroll
            for (int q = 0; q < 4; q++) {
                float2 f = __bfloat1622float2(p2[q]);
                kps[l][m8 + q * 2 + 0] = f.x;
                kps[l][m8 + q * 2 + 1] = f.y;
            }
        }
        for (int idx = tid; idx < 16 * 16; idx += 256) {
            int l = idx >> 4, d4 = (idx & 15) * 4;
            *(float4*)&vs[l][d4] =
                *(const float4*)(v + (size_t)(b * LQ + lbase + lc + l) * DQ + h * HDQ + d4);
        }
        __syncthreads();
#pragma unroll
        for (int l = 0; l < 16; l++) {
            float a[8], bb[8];
#pragma unroll
            for (int i = 0; i < 8; i++) a[i] = kps[l][mi + i];
#pragma unroll
            for (int j = 0; j < 8; j++) bb[j] = vs[l][di + j];
#pragma unroll
            for (int i = 0; i < 8; i++)
#pragma unroll
                for (int j = 0; j < 8; j++)
                    acc[i][j] = fmaf(a[i], bb[j], acc[i][j]);
            if (owner)
#pragma unroll
                for (int i = 0; i < 8; i++) ks[i] += a[i];
        }
        __syncthreads();
    }
#pragma unroll
    for (int i = 0; i < 8; i++)
#pragma unroll
        for (int j = 0; j < 8; j++)
            atomicAdd(&g_kv[((size_t)bh * MQ + mi + i) * HDQ + di + j], acc[i][j]);
    if (owner)
#pragma unroll
        for (int i = 0; i < 8; i++)
            atomicAdd(&g_ksum[bh * MQ + mi + i], ks[i]);
}

// ---------------- z (bf16 qp) ----------------
__global__ void __launch_bounds__(256) z_kernel(const bf16* __restrict__ qp)
{
    int row = blockIdx.x * 8 + (threadIdx.x >> 5);
    int lane = threadIdx.x & 31;
    int bh = row >> 12;
    const bf16* qr = qp + (size_t)row * MQ;
    const float* kss = g_ksum + bh * MQ;
    float s = 0.f;
#pragma unroll
    for (int m0 = 0; m0 < MQ; m0 += 64) {
        int m = m0 + lane * 2;
        __nv_bfloat162 q2 = *(const __nv_bfloat162*)(qr + m);
        float2 f = __bfloat1622float2(q2);
        s = fmaf(f.x, kss[m], s);
        s = fmaf(f.y, kss[m + 1], s);
    }
#pragma unroll
    for (int o = 16; o > 0; o >>= 1) s += __shfl_xor_sync(0xffffffffu, s, o);
    if (lane == 0) g_z[row] = 1.f / (s + 1e-6f);
}

// ---------------- attn combine (bf16 qp) -> split bf16 ---------------------
__global__ void __launch_bounds__(256) attn_kernel(
    const bf16* __restrict__ qp, bf16* __restrict__ out_hi, bf16* __restrict__ out_lo)
{
    int bh = blockIdx.y;
    int h = bh & (HQ - 1), b = bh >> 4;
    int l0 = blockIdx.x * 128;
    __shared__ float qs[128][36];
    __shared__ float kvs[32][HDQ + 4];
    int tid = threadIdx.x;
    int ti = (tid >> 3) << 2;
    int di = (tid & 7) << 3;
    float acc[4][8];
#pragma unroll
    for (int i = 0; i < 4; i++)
#pragma unroll
        for (int j = 0; j < 8; j++) acc[i][j] = 0.f;

    for (int m0 = 0; m0 < MQ; m0 += 32) {
        // qp tile: 128 rows x 32 m bf16 -> 512 chunks of 8
        for (int idx = tid; idx < 128 * 4; idx += 256) {
            int t = idx >> 2, mq = (idx & 3) * 8;
            uint4 r = *(const uint4*)(qp + ((size_t)bh * LQ + l0 + t) * MQ + m0 + mq);
            const __nv_bfloat162* p2 = (const __nv_bfloat162*)&r;
#pragma unroll
            for (int q = 0; q < 4; q++) {
                float2 f = __bfloat1622float2(p2[q]);
                qs[t][mq + q * 2 + 0] = f.x;
                qs[t][mq + q * 2 + 1] = f.y;
            }
        }
        for (int idx = tid; idx < 32 * 16; idx += 256) {
            int m = idx >> 4, dq = (idx & 15) * 4;
            *(float4*)&kvs[m][dq] =
                *(const float4*)(&g_kv[((size_t)bh * MQ + m0 + m) * HDQ + dq]);
        }
        __syncthreads();
#pragma unroll 4
        for (int m = 0; m < 32; m++) {
            float a[4], bb[8];
#pragma unroll
            for (int i = 0; i < 4; i++) a[i] = qs[ti + i][m];
#pragma unroll
            for (int j = 0; j < 8; j++) bb[j] = kvs[m][di + j];
#pragma unroll
            for (int i = 0; i < 4; i++)
#pragma unroll
                for (int j = 0; j < 8; j++)
                    acc[i][j] = fmaf(a[i], bb[j], acc[i][j]);
        }
        __syncthreads();
    }
#pragma unroll
    for (int i = 0; i < 4; i++) {
        float zz = g_z[bh * LQ + l0 + ti + i];
        size_t token = (size_t)(b * LQ + l0 + ti + i);
        size_t base = token * DQ + h * HDQ + di;
#pragma unroll
        for (int j = 0; j < 8; j += 2) {
            float v0 = acc[i][j] * zz, v1 = acc[i][j + 1] * zz;
            bf16 h0, l0b, h1, l1;
            split_bf16(v0, h0, l0b);
            split_bf16(v1, h1, l1);
            *(uint32_t*)(out_hi + base + j) =
                (uint32_t)__bfloat16_as_ushort(h0) | ((uint32_t)__bfloat16_as_ushort(h1) << 16);
            *(uint32_t*)(out_lo + base + j) =
                (uint32_t)__bfloat16_as_ushort(l0b) | ((uint32_t)__bfloat16_as_ushort(l1) << 16);
        }
    }
}

// ---------------------------------------------------------------------------
extern "C" void kernel_launch(void* const* d_in, const int* in_sizes, int n_in,
                              void* d_out, int out_size)
{
    const float* x     = (const float*)d_in[0];
    const float* ln1_w = (const float*)d_in[1];
    const float* ln1_b = (const float*)d_in[2];
    const float* ln2_w = (const float*)d_in[3];
    const float* ln2_b = (const float*)d_in[4];
    const float* Wq    = (const float*)d_in[5];
    const float* bq    = (const float*)d_in[6];
    const float* Wk    = (const float*)d_in[7];
    const float* bk    = (const float*)d_in[8];
    const float* Wv    = (const float*)d_in[9];
    const float* bv    = (const float*)d_in[10];
    const float* Wo    = (const float*)d_in[11];
    const float* bo    = (const float*)d_in[12];
    const float* W1    = (const float*)d_in[13];
    const float* b1    = (const float*)d_in[14];
    const float* W2    = (const float*)d_in[15];
    const float* b2    = (const float*)d_in[16];
    const float* proj  = (const float*)d_in[17];
    float* out = (float*)d_out;

    float *p_q, *p_k, *p_v, *p_kv, *p_ksum, *p_x2;
    bf16 *p_qp, *p_kp;
    bf16 *p_hh, *p_hl, *p_ah, *p_al;
    __half *p_h2, *p_midh, *p_w1h, *p_w2h;
    bf16 *p_wq_h, *p_wq_l, *p_wk_h, *p_wk_l, *p_wv_h, *p_wv_l, *p_wo_h, *p_wo_l;
    cudaGetSymbolAddress((void**)&p_q,    g_q);
    cudaGetSymbolAddress((void**)&p_k,    g_k);
    cudaGetSymbolAddress((void**)&p_v,    g_v);
    cudaGetSymbolAddress((void**)&p_qp,   g_qp);
    cudaGetSymbolAddress((void**)&p_kp,   g_kp);
    cudaGetSymbolAddress((void**)&p_kv,   g_kv);
    cudaGetSymbolAddress((void**)&p_ksum, g_ksum);
    cudaGetSymbolAddress((void**)&p_x2,   g_x2);
    cudaGetSymbolAddress((void**)&p_hh,   g_h_hi);
    cudaGetSymbolAddress((void**)&p_hl,   g_h_lo);
    cudaGetSymbolAddress((void**)&p_ah,   g_attn_hi);
    cudaGetSymbolAddress((void**)&p_al,   g_attn_lo);
    cudaGetSymbolAddress((void**)&p_h2,   g_h2);
    cudaGetSymbolAddress((void**)&p_midh, g_midh);
    cudaGetSymbolAddress((void**)&p_w1h,  g_w1h);
    cudaGetSymbolAddress((void**)&p_w2h,  g_w2h);
    cudaGetSymbolAddress((void**)&p_wq_h, g_wq_hi); cudaGetSymbolAddress((void**)&p_wq_l, g_wq_lo);
    cudaGetSymbolAddress((void**)&p_wk_h, g_wk_hi); cudaGetSymbolAddress((void**)&p_wk_l, g_wk_lo);
    cudaGetSymbolAddress((void**)&p_wv_h, g_wv_hi); cudaGetSymbolAddress((void**)&p_wv_l, g_wv_lo);
    cudaGetSymbolAddress((void**)&p_wo_h, g_wo_hi); cudaGetSymbolAddress((void**)&p_wo_l, g_wo_lo);

    const int SMEM_GEMM = 2 * STAGE_B;      // 80KB
    const int SMEM_H    = 2 * HSTAGE_B;     // 40KB
    cudaFuncSetAttribute(tc_gemm2<0>, cudaFuncAttributeMaxDynamicSharedMemorySize, SMEM_GEMM);
    cudaFuncSetAttribute(tc_gemm2<1>, cudaFuncAttributeMaxDynamicSharedMemorySize, SMEM_GEMM);
    cudaFuncSetAttribute(tc_gemm_h<1>, cudaFuncAttributeMaxDynamicSharedMemorySize, SMEM_H);
    cudaFuncSetAttribute(tc_gemm_h<2>, cudaFuncAttributeMaxDynamicSharedMemorySize, SMEM_H);

    dim3 gD(DQ / 128, NTOK / 128);
    dim3 g4D(4 * DQ / 128, NTOK / 128);

    // weight conversions
    wconv_kernel<<<dim3(DQ / 32, DQ / 32), 256>>>(Wq, p_wq_h, p_wq_l, DQ, DQ);
    wconv_kernel<<<dim3(DQ / 32, DQ / 32), 256>>>(Wk, p_wk_h, p_wk_l, DQ, DQ);
    wconv_kernel<<<dim3(DQ / 32, DQ / 32), 256>>>(Wv, p_wv_h, p_wv_l, DQ, DQ);
    wconv_kernel<<<dim3(DQ / 32, DQ / 32), 256>>>(Wo, p_wo_h, p_wo_l, DQ, DQ);
    wconv_h_kernel<<<dim3(4 * DQ / 32, DQ / 32), 256>>>(W1, p_w1h, DQ, 4 * DQ);
    wconv_h_kernel<<<dim3(DQ / 32, 4 * DQ / 32), 256>>>(W2, p_w2h, 4 * DQ, DQ);

    // LN1 -> split h
    ln_kernel<<<NTOK, 256>>>(x, ln1_w, ln1_b, p_hh, p_hl);
    // QKV (bf16 3-term)
    tc_gemm2<0><<<gD, 256, SMEM_GEMM>>>(p_hh, p_hl, p_wq_h, p_wq_l, bq, nullptr, p_q, DQ, DQ);
    tc_gemm2<0><<<gD, 256, SMEM_GEMM>>>(p_hh, p_hl, p_wk_h, p_wk_l, bk, nullptr, p_k, DQ, DQ);
    tc_gemm2<0><<<gD, 256, SMEM_GEMM>>>(p_hh, p_hl, p_wv_h, p_wv_l, bv, nullptr, p_v, DQ, DQ);
    // performer feature maps -> bf16
    feature_kernel<<<dim3(LQ / 64, NH), 256>>>(p_q, proj, p_qp);
    feature_kernel<<<dim3(LQ / 64, NH), 256>>>(p_k, proj, p_kp);
    // kv + k_sum
    cudaMemsetAsync(p_kv,   0, (size_t)NH * MQ * HDQ * sizeof(float));
    cudaMemsetAsync(p_ksum, 0, (size_t)NH * MQ * sizeof(float));
    kv_kernel<<<dim3(8, NH), 256>>>(p_kp, p_v);
    // normalizer z
    z_kernel<<<NH * LQ / 8, 256>>>(p_qp);
    // attention combine -> split attn
    attn_kernel<<<dim3(LQ / 128, NH), 256>>>(p_qp, p_ah, p_al);
    // output proj + residual (bf16 3-term)
    tc_gemm2<1><<<gD, 256, SMEM_GEMM>>>(p_ah, p_al, p_wo_h, p_wo_l, bo, x, p_x2, DQ, DQ);
    // LN2 -> single fp16
    ln_kernel_h<<<NTOK, 256>>>(p_x2, ln2_w, ln2_b, p_h2);
    // MLP up + gelu (fp16 single) -> fp16 mid
    tc_gemm_h<2><<<g4D, 256, SMEM_H>>>(p_h2, p_w1h, b1, nullptr, nullptr, p_midh, 4 * DQ, DQ);
    // MLP down + residual (fp16 single) -> out
    tc_gemm_h<1><<<gD, 256, SMEM_H>>>(p_midh, p_w2h, b2, p_x2, out, nullptr, DQ, 4 * DQ);
}